// round 6
// baseline (speedup 1.0000x reference)
#include <cuda_runtime.h>
#include <math.h>

#define NN 50000
#define EE 300000
#define CCH 256
#define HH 8
#define ND 256
#define FSCALE 0.17677669529663687f   // 1/sqrt(32)

// ---------------- static device scratch (no runtime allocation) -------------
__device__ float    g_Qd[ND*CCH];      // Q rows for the 256 dst nodes
__device__ float    g_qt[ND*HH*CCH];   // per-(dst,head) query folded through Wk
__device__ float    g_qb[ND*HH];       // per-(dst,head) bias term (Q . bk)
__device__ float    g_WqT[CCH*CCH];
__device__ float    g_WvT[CCH*CCH];
__device__ int      g_hist[ND];
__device__ int      g_base[ND];
__device__ int      g_off[ND];
__device__ int      g_list[EE];        // edge ids with src < 256
__device__ int      g_nlist;
__device__ int      g_ssrc[EE];        // src, sorted by dst bucket
__device__ int      g_sspd[EE];        // spd bucket, sorted by dst bucket
__device__ unsigned g_F1[ND*8];        // 256x256 bit frontier matrices
__device__ unsigned g_F2[ND*8];
__device__ unsigned g_F3[ND*8];
__device__ float    g_agg[ND*CCH];     // attention output rows (incl. bv)

// ---------------- init ------------------------------------------------------
__global__ void k_zero() {
    int i = blockIdx.x * blockDim.x + threadIdx.x;
    if (i < ND*8) { g_F1[i] = 0u; g_F2[i] = 0u; g_F3[i] = 0u; }
    if (i < ND)   g_hist[i] = 0;
    if (i == 0)   g_nlist = 0;
}

// transpose Wq -> g_WqT (z=0) and Wv -> g_WvT (z=1)
__global__ void k_transpose(const float* __restrict__ Wq,
                            const float* __restrict__ Wv) {
    __shared__ float t[32][33];
    const float* W = blockIdx.z ? Wv : Wq;
    float*       O = blockIdx.z ? g_WvT : g_WqT;
    int x0 = blockIdx.x * 32, y0 = blockIdx.y * 32;
    t[threadIdx.y][threadIdx.x] = W[(y0 + threadIdx.y) * CCH + x0 + threadIdx.x];
    __syncthreads();
    O[(x0 + threadIdx.y) * CCH + y0 + threadIdx.x] = t[threadIdx.x][threadIdx.y];
}

// dst histogram, src<256 edge list, BFS frontier F1 seed
__global__ void k_prep(const int* __restrict__ src, const int* __restrict__ dst) {
    int i = blockIdx.x * blockDim.x + threadIdx.x;
    if (i >= EE) return;
    int s = src[i], d = dst[i];
    atomicAdd(&g_hist[d], 1);
    if (s < ND) {
        int p = atomicAdd(&g_nlist, 1);
        g_list[p] = i;
        atomicOr(&g_F1[d * 8 + (s >> 5)], 1u << (s & 31));   // F1[row=d, col=s]
    }
}

__global__ void k_scan() {
    __shared__ int sm[ND];
    int t = threadIdx.x;
    sm[t] = g_hist[t];
    __syncthreads();
    if (t == 0) {
        int acc = 0;
        for (int i = 0; i < ND; i++) { int v = sm[i]; sm[i] = acc; acc += v; }
    }
    __syncthreads();
    g_base[t] = sm[t];
    g_off[t]  = sm[t];
}

// BFS step over the src<256 edges: step==2: F2=bin(A@F1); step==3: F3=bin(A@F2)
__global__ void k_bfs(const int* __restrict__ src, const int* __restrict__ dst, int step) {
    int i = blockIdx.x * blockDim.x + threadIdx.x;
    if (i >= g_nlist) return;
    int e = g_list[i];
    int s = src[e], d = dst[e];
    const unsigned* Fp = (step == 2) ? g_F1 : g_F2;
    unsigned*       Fn = (step == 2) ? g_F2 : g_F3;
#pragma unroll
    for (int w = 0; w < 8; w++) {
        unsigned v = Fp[s * 8 + w];
        if (v) atomicOr(&Fn[d * 8 + w], v);
    }
}

// counting-sort scatter by dst, with inline spd bucket lookup
__global__ void k_scatter(const int* __restrict__ src, const int* __restrict__ dst) {
    int i = blockIdx.x * blockDim.x + threadIdx.x;
    if (i >= EE) return;
    int s = src[i], d = dst[i];
    int p = atomicAdd(&g_off[d], 1);
    g_ssrc[p] = s;
    int spd = 4;
    if (s < ND) {
        unsigned msk = 1u << (d & 31);
        int w = d >> 5;
        if      (g_F1[s * 8 + w] & msk) spd = 1;
        else if (g_F2[s * 8 + w] & msk) spd = 2;
        else if (g_F3[s * 8 + w] & msk) spd = 3;
    }
    g_sspd[p] = spd;
}

// Qd[d,:] = x[d] @ Wq^T + bq   (one CTA per dst node)
__global__ void k_qd(const float* __restrict__ x, const float* __restrict__ bq) {
    int d = blockIdx.x, c = threadIdx.x;
    __shared__ float xs[CCH];
    xs[c] = x[d * CCH + c];
    __syncthreads();
    float acc = bq[c];
#pragma unroll 4
    for (int k = 0; k < CCH; k++) acc = fmaf(xs[k], g_WqT[k * CCH + c], acc);
    g_Qd[d * CCH + c] = acc;
}

// qt[d,h,:] = SCALE * Qd[d,h-block] @ Wk_h ;  qb[d,h] = SCALE * Qd . bk_h
__global__ void k_qt(const float* __restrict__ Wk, const float* __restrict__ bk) {
    int d = blockIdx.x, k = threadIdx.x;
    __shared__ float qh[32];
    for (int h = 0; h < HH; h++) {
        __syncthreads();
        if (k < 32) qh[k] = g_Qd[d * CCH + h * 32 + k];
        __syncthreads();
        float acc = 0.f;
#pragma unroll 8
        for (int j = 0; j < 32; j++)
            acc = fmaf(qh[j], Wk[(h * 32 + j) * CCH + k], acc);
        g_qt[(d * HH + h) * CCH + k] = FSCALE * acc;
        if (k == 0) {
            float qb = 0.f;
            for (int j = 0; j < 32; j++) qb += qh[j] * bk[h * 32 + j];
            g_qb[d * HH + h] = FSCALE * qb;
        }
    }
}

// main: one CTA per dst, warp per head, online softmax + B accumulation,
// in-CTA Wv epilogue.
__global__ void __launch_bounds__(256) k_main(const float* __restrict__ x,
                                              const float* __restrict__ spd_w,
                                              const float* __restrict__ bv) {
    int d = blockIdx.x;
    int tid = threadIdx.x;
    int h = tid >> 5, lane = tid & 31;
    __shared__ float spdw[48];
    __shared__ float Bs[HH * CCH];
    if (tid < 40) spdw[tid] = spd_w[tid];

    const float4* qp = (const float4*)(g_qt + (d * HH + h) * CCH) + lane * 2;
    float4 qA = qp[0], qB = qp[1];
    float qbias = g_qb[d * HH + h];
    __syncthreads();

    int p    = g_base[d];
    int pend = p + g_hist[d];

    float m = -1e30f, ssum = 0.f;
    float acc[8];
#pragma unroll
    for (int r = 0; r < 8; r++) acc[r] = 0.f;

    // pairwise online softmax (2-edge unroll for ILP over the shfl chains)
    for (; p + 2 <= pend; p += 2) {
        int s1 = g_ssrc[p],   s2 = g_ssrc[p + 1];
        int b1 = g_sspd[p],   b2 = g_sspd[p + 1];
        const float4* xp1 = (const float4*)(x + s1 * CCH) + lane * 2;
        const float4* xp2 = (const float4*)(x + s2 * CCH) + lane * 2;
        float4 u0 = xp1[0], u1 = xp1[1];
        float4 v0 = xp2[0], v1 = xp2[1];

        float d1 = qA.x*u0.x + qA.y*u0.y + qA.z*u0.z + qA.w*u0.w
                 + qB.x*u1.x + qB.y*u1.y + qB.z*u1.z + qB.w*u1.w;
        float d2 = qA.x*v0.x + qA.y*v0.y + qA.z*v0.z + qA.w*v0.w
                 + qB.x*v1.x + qB.y*v1.y + qB.z*v1.z + qB.w*v1.w;
#pragma unroll
        for (int o = 16; o >= 1; o >>= 1) {
            d1 += __shfl_xor_sync(0xffffffffu, d1, o);
            d2 += __shfl_xor_sync(0xffffffffu, d2, o);
        }
        float sc1 = d1 + qbias + spdw[b1 * 8 + h];
        float sc2 = d2 + qbias + spdw[b2 * 8 + h];
        float mn  = fmaxf(m, fmaxf(sc1, sc2));
        float corr = __expf(m - mn);
        float e1 = __expf(sc1 - mn);
        float e2 = __expf(sc2 - mn);
        ssum = ssum * corr + e1 + e2;
        float uu[8] = {u0.x,u0.y,u0.z,u0.w,u1.x,u1.y,u1.z,u1.w};
        float vv[8] = {v0.x,v0.y,v0.z,v0.w,v1.x,v1.y,v1.z,v1.w};
#pragma unroll
        for (int r = 0; r < 8; r++)
            acc[r] = fmaf(e2, vv[r], fmaf(e1, uu[r], acc[r] * corr));
        m = mn;
    }
    if (p < pend) {  // odd tail
        int s1 = g_ssrc[p];
        int b1 = g_sspd[p];
        const float4* xp1 = (const float4*)(x + s1 * CCH) + lane * 2;
        float4 u0 = xp1[0], u1 = xp1[1];
        float d1 = qA.x*u0.x + qA.y*u0.y + qA.z*u0.z + qA.w*u0.w
                 + qB.x*u1.x + qB.y*u1.y + qB.z*u1.z + qB.w*u1.w;
#pragma unroll
        for (int o = 16; o >= 1; o >>= 1)
            d1 += __shfl_xor_sync(0xffffffffu, d1, o);
        float sc1 = d1 + qbias + spdw[b1 * 8 + h];
        float mn  = fmaxf(m, sc1);
        float corr = __expf(m - mn);
        float e1 = __expf(sc1 - mn);
        ssum = ssum * corr + e1;
        float uu[8] = {u0.x,u0.y,u0.z,u0.w,u1.x,u1.y,u1.z,u1.w};
#pragma unroll
        for (int r = 0; r < 8; r++)
            acc[r] = fmaf(e1, uu[r], acc[r] * corr);
    }

    float inv = (ssum > 0.f) ? (1.f / ssum) : 0.f;
    int bsb = h * CCH + lane * 8;
#pragma unroll
    for (int r = 0; r < 8; r++) Bs[bsb + r] = acc[r] * inv;
    __syncthreads();

    // epilogue: out[d, c] = Wv[c,:] . B[head(c),:] + bv[c]
    int hh = tid >> 5;
    float o = bv[tid];
    const float* Bp = Bs + hh * CCH;
    const float* Wp = g_WvT + tid;
#pragma unroll 4
    for (int k = 0; k < CCH; k++) o = fmaf(Wp[k * CCH], Bp[k], o);
    g_agg[d * CCH + tid] = o;
}

// LayerNorm over v = agg + x (deg is constant per row -> cancels exactly)
__global__ void __launch_bounds__(256) k_ln(const float* __restrict__ x,
                                            const float* __restrict__ gamma,
                                            const float* __restrict__ beta,
                                            float* __restrict__ out) {
    int row  = blockIdx.x * 8 + (threadIdx.x >> 5);
    int lane = threadIdx.x & 31;
    if (row >= NN) return;
    const float4* xp = (const float4*)(x + (size_t)row * CCH) + lane * 2;
    float4 A = xp[0], B = xp[1];
    float v[8] = {A.x, A.y, A.z, A.w, B.x, B.y, B.z, B.w};
    if (row < ND) {
        const float4* ap = (const float4*)(g_agg + row * CCH) + lane * 2;
        float4 C = ap[0], D = ap[1];
        v[0] += C.x; v[1] += C.y; v[2] += C.z; v[3] += C.w;
        v[4] += D.x; v[5] += D.y; v[6] += D.z; v[7] += D.w;
    }
    float s = 0.f;
#pragma unroll
    for (int r = 0; r < 8; r++) s += v[r];
#pragma unroll
    for (int o = 16; o >= 1; o >>= 1) s += __shfl_xor_sync(0xffffffffu, s, o);
    float mu = s * (1.f / 256.f);
    float q = 0.f;
#pragma unroll
    for (int r = 0; r < 8; r++) { float t = v[r] - mu; q += t * t; }
#pragma unroll
    for (int o = 16; o >= 1; o >>= 1) q += __shfl_xor_sync(0xffffffffu, q, o);
    float var = q * (1.f / 256.f);
    float rs = rsqrtf(var + 1e-5f);

    const float4* gp = (const float4*)gamma + lane * 2;
    const float4* bp = (const float4*)beta  + lane * 2;
    float4 G0 = gp[0], G1 = gp[1], B0 = bp[0], B1 = bp[1];
    float g[8]  = {G0.x,G0.y,G0.z,G0.w,G1.x,G1.y,G1.z,G1.w};
    float be[8] = {B0.x,B0.y,B0.z,B0.w,B1.x,B1.y,B1.z,B1.w};
    float r0[8];
#pragma unroll
    for (int r = 0; r < 8; r++) r0[r] = (v[r] - mu) * rs * g[r] + be[r];
    float4* op = (float4*)(out + (size_t)row * CCH) + lane * 2;
    op[0] = make_float4(r0[0], r0[1], r0[2], r0[3]);
    op[1] = make_float4(r0[4], r0[5], r0[6], r0[7]);
}

// ---------------- launch ----------------------------------------------------
extern "C" void kernel_launch(void* const* d_in, const int* in_sizes, int n_in,
                              void* d_out, int out_size) {
    const float* x     = (const float*)d_in[0];
    const int*   src   = (const int*)  d_in[1];
    const int*   dst   = (const int*)  d_in[2];
    const float* Wq    = (const float*)d_in[3];
    const float* bq    = (const float*)d_in[4];
    const float* Wk    = (const float*)d_in[5];
    const float* bk    = (const float*)d_in[6];
    const float* Wv    = (const float*)d_in[7];
    const float* bv    = (const float*)d_in[8];
    const float* spd_w = (const float*)d_in[9];
    const float* gamma = (const float*)d_in[10];
    const float* beta  = (const float*)d_in[11];
    float* out = (float*)d_out;
    (void)in_sizes; (void)n_in; (void)out_size;

    int eb = (EE + 255) / 256;
    k_zero<<<8, 256>>>();
    k_transpose<<<dim3(8, 8, 2), dim3(32, 32)>>>(Wq, Wv);
    k_prep<<<eb, 256>>>(src, dst);
    k_scan<<<1, 256>>>();
    k_bfs<<<eb, 256>>>(src, dst, 2);
    k_bfs<<<eb, 256>>>(src, dst, 3);
    k_scatter<<<eb, 256>>>(src, dst);
    k_qd<<<ND, 256>>>(x, bq);
    k_qt<<<ND, 256>>>(Wk, bk);
    k_main<<<ND, 256>>>(x, spd_w, bv);
    k_ln<<<(NN + 7) / 8, 256>>>(x, gamma, beta, out);
}

// round 7
// speedup vs baseline: 1.7641x; 1.7641x over previous
#include <cuda_runtime.h>
#include <math.h>

#define NN 50000
#define EE 300000
#define CCH 256
#define HH 8
#define ND 256
#define NP 8                     // partial CTAs per dst in k_main
#define PADH 32                  // counter padding (ints) to spread L2 slices
#define FSCALE 0.17677669529663687f   // 1/sqrt(32)

// ---------------- static device scratch (no runtime allocation) -------------
__device__ float    g_Qd[ND*CCH];        // Q rows for the 256 dst nodes
__device__ float    g_qt[ND*HH*CCH];     // per-(dst,head) query folded through Wk
__device__ float    g_qb[ND*HH];         // per-(dst,head) bias term
__device__ float    g_WqT[CCH*CCH];
__device__ float    g_WvT[CCH*CCH];
__device__ int      g_histP[ND*PADH];    // padded counters
__device__ int      g_offP[ND*PADH];
__device__ int      g_base[ND];
__device__ int      g_cnt[ND];
__device__ int      g_list[EE];          // edge ids with src < 256
__device__ int      g_nlist;
__device__ int      g_pack[EE];          // (spd<<20)|src, sorted by dst bucket
__device__ unsigned g_F1[ND*8];          // 256x256 bit frontier matrices
__device__ unsigned g_F2[ND*8];
__device__ unsigned g_F3[ND*8];
__device__ float    g_pB[ND*NP*HH*CCH];  // partial weighted-x sums (16 MB)
__device__ float    g_pS[ND*NP*HH];      // partial exp-sums
__device__ float    g_agg[ND*CCH];       // attention output rows (incl. bv)

// ---------------- init ------------------------------------------------------
__global__ void k_zero() {
    int i = blockIdx.x * blockDim.x + threadIdx.x;
    if (i < ND*PADH) g_histP[i] = 0;
    if (i < ND*8) { g_F1[i] = 0u; g_F2[i] = 0u; g_F3[i] = 0u; }
    if (i == 0)   g_nlist = 0;
}

// transpose Wq -> g_WqT (z=0) and Wv -> g_WvT (z=1)
__global__ void k_transpose(const float* __restrict__ Wq,
                            const float* __restrict__ Wv) {
    __shared__ float t[32][33];
    const float* W = blockIdx.z ? Wv : Wq;
    float*       O = blockIdx.z ? g_WvT : g_WqT;
    int x0 = blockIdx.x * 32, y0 = blockIdx.y * 32;
    t[threadIdx.y][threadIdx.x] = W[(y0 + threadIdx.y) * CCH + x0 + threadIdx.x];
    __syncthreads();
    O[(x0 + threadIdx.y) * CCH + y0 + threadIdx.x] = t[threadIdx.x][threadIdx.y];
}

// dst histogram via shared-memory aggregation; src<256 list; F1 seed
__global__ void __launch_bounds__(256) k_prep(const int* __restrict__ src,
                                              const int* __restrict__ dst) {
    __shared__ int sh[ND];
    int t = threadIdx.x;
    sh[t] = 0;
    __syncthreads();
    int chunk = (EE + gridDim.x - 1) / gridDim.x;
    int start = blockIdx.x * chunk;
    int end   = min(EE, start + chunk);
    for (int i = start + t; i < end; i += 256) {
        int d = dst[i], s = src[i];
        atomicAdd(&sh[d], 1);
        if (s < ND) {
            int p = atomicAdd(&g_nlist, 1);
            g_list[p] = i;
            atomicOr(&g_F1[d * 8 + (s >> 5)], 1u << (s & 31));
        }
    }
    __syncthreads();
    if (sh[t]) atomicAdd(&g_histP[t * PADH], sh[t]);
}

// parallel exclusive scan over 256 counters
__global__ void k_scan() {
    int t = threadIdx.x, lane = t & 31, w = t >> 5;
    int v = g_histP[t * PADH];
    int xs = v;
#pragma unroll
    for (int o = 1; o < 32; o <<= 1) {
        int y = __shfl_up_sync(0xffffffffu, xs, o);
        if (lane >= o) xs += y;
    }
    __shared__ int ws[8], wb[8];
    if (lane == 31) ws[w] = xs;
    __syncthreads();
    if (t == 0) { int a = 0; for (int i = 0; i < 8; i++) { wb[i] = a; a += ws[i]; } }
    __syncthreads();
    int excl = xs + wb[w] - v;
    g_base[t] = excl;
    g_cnt[t]  = v;
    g_offP[t * PADH] = excl;
}

// BFS step over the src<256 edges
__global__ void k_bfs(const int* __restrict__ src, const int* __restrict__ dst, int step) {
    int i = blockIdx.x * blockDim.x + threadIdx.x;
    if (i >= g_nlist) return;
    int e = g_list[i];
    int s = src[e], d = dst[e];
    const unsigned* Fp = (step == 2) ? g_F1 : g_F2;
    unsigned*       Fn = (step == 2) ? g_F2 : g_F3;
#pragma unroll
    for (int w = 0; w < 8; w++) {
        unsigned v = Fp[s * 8 + w];
        if (v) atomicOr(&Fn[d * 8 + w], v);
    }
}

// counting-sort scatter (block-reserved ranges, shared-memory offsets),
// packing (spd<<20)|src per edge
__global__ void __launch_bounds__(256) k_scatter(const int* __restrict__ src,
                                                 const int* __restrict__ dst) {
    __shared__ int shCnt[ND];
    __shared__ int shBase[ND];
    int t = threadIdx.x;
    shCnt[t] = 0;
    __syncthreads();
    int chunk = (EE + gridDim.x - 1) / gridDim.x;
    int start = blockIdx.x * chunk;
    int end   = min(EE, start + chunk);
    for (int i = start + t; i < end; i += 256) atomicAdd(&shCnt[dst[i]], 1);
    __syncthreads();
    int c = shCnt[t];
    shBase[t] = c ? atomicAdd(&g_offP[t * PADH], c) : 0;
    __syncthreads();
    shCnt[t] = 0;
    __syncthreads();
    for (int i = start + t; i < end; i += 256) {
        int d = dst[i], s = src[i];
        int loc = atomicAdd(&shCnt[d], 1);
        int p = shBase[d] + loc;
        int spd = 4;
        if (s < ND) {
            unsigned msk = 1u << (d & 31);
            int w = d >> 5;
            if      (g_F1[s * 8 + w] & msk) spd = 1;
            else if (g_F2[s * 8 + w] & msk) spd = 2;
            else if (g_F3[s * 8 + w] & msk) spd = 3;
        }
        g_pack[p] = s | (spd << 20);
    }
}

// Qd[d,:] = x[d] @ Wq^T + bq
__global__ void k_qd(const float* __restrict__ x, const float* __restrict__ bq) {
    int d = blockIdx.x, c = threadIdx.x;
    __shared__ float xs[CCH];
    xs[c] = x[d * CCH + c];
    __syncthreads();
    float acc = bq[c];
#pragma unroll 4
    for (int k = 0; k < CCH; k++) acc = fmaf(xs[k], g_WqT[k * CCH + c], acc);
    g_Qd[d * CCH + c] = acc;
}

// qt[d,h,:] = SCALE * Qd[d, h-block] @ Wk_h ;  qb[d,h] = SCALE * Qd . bk_h
__global__ void k_qt(const float* __restrict__ Wk, const float* __restrict__ bk) {
    int d = blockIdx.x, k = threadIdx.x;
    __shared__ float qh[32];
    for (int h = 0; h < HH; h++) {
        __syncthreads();
        if (k < 32) qh[k] = g_Qd[d * CCH + h * 32 + k];
        __syncthreads();
        float acc = 0.f;
#pragma unroll 8
        for (int j = 0; j < 32; j++)
            acc = fmaf(qh[j], Wk[(h * 32 + j) * CCH + k], acc);
        g_qt[(d * HH + h) * CCH + k] = FSCALE * acc;
        if (k == 0) {
            float qb = 0.f;
            for (int j = 0; j < 32; j++) qb += qh[j] * bk[h * 32 + j];
            g_qb[d * HH + h] = FSCALE * qb;
        }
    }
}

// main: NP CTAs per dst, warp per head, NO max (scores are O(1), exp safe),
// purely additive partial exp-sums + weighted-x accumulators.
__global__ void __launch_bounds__(256) k_main(const float* __restrict__ x,
                                              const float* __restrict__ spd_w) {
    int d = blockIdx.x >> 3, part = blockIdx.x & (NP - 1);
    int tid = threadIdx.x;
    int h = tid >> 5, lane = tid & 31;
    __shared__ float spdw[40];
    if (tid < 40) spdw[tid] = spd_w[tid];

    const float4* qp = (const float4*)(g_qt + (d * HH + h) * CCH) + lane * 2;
    float4 qA = qp[0], qB = qp[1];
    float qbias = g_qb[d * HH + h];
    __syncthreads();

    int b0 = g_base[d], cnt = g_cnt[d];
    int per = (cnt + NP - 1) >> 3;
    int p    = b0 + part * per;
    int pend = b0 + min(cnt, (part + 1) * per);

    float ssum = 0.f;
    float acc[8];
#pragma unroll
    for (int r = 0; r < 8; r++) acc[r] = 0.f;

    for (; p + 2 <= pend; p += 2) {
        int pk1 = g_pack[p], pk2 = g_pack[p + 1];
        int s1 = pk1 & 0xFFFFF, s2 = pk2 & 0xFFFFF;
        const float4* xp1 = (const float4*)(x + s1 * CCH) + lane * 2;
        const float4* xp2 = (const float4*)(x + s2 * CCH) + lane * 2;
        float4 u0 = xp1[0], u1 = xp1[1];
        float4 v0 = xp2[0], v1 = xp2[1];

        float d1 = qA.x*u0.x + qA.y*u0.y + qA.z*u0.z + qA.w*u0.w
                 + qB.x*u1.x + qB.y*u1.y + qB.z*u1.z + qB.w*u1.w;
        float d2 = qA.x*v0.x + qA.y*v0.y + qA.z*v0.z + qA.w*v0.w
                 + qB.x*v1.x + qB.y*v1.y + qB.z*v1.z + qB.w*v1.w;
#pragma unroll
        for (int o = 16; o >= 1; o >>= 1) {
            d1 += __shfl_xor_sync(0xffffffffu, d1, o);
            d2 += __shfl_xor_sync(0xffffffffu, d2, o);
        }
        float e1 = __expf(d1 + qbias + spdw[(pk1 >> 20) * 8 + h]);
        float e2 = __expf(d2 + qbias + spdw[(pk2 >> 20) * 8 + h]);
        ssum += e1 + e2;
        float uu[8] = {u0.x,u0.y,u0.z,u0.w,u1.x,u1.y,u1.z,u1.w};
        float vv[8] = {v0.x,v0.y,v0.z,v0.w,v1.x,v1.y,v1.z,v1.w};
#pragma unroll
        for (int r = 0; r < 8; r++)
            acc[r] = fmaf(e2, vv[r], fmaf(e1, uu[r], acc[r]));
    }
    if (p < pend) {  // odd tail
        int pk1 = g_pack[p];
        int s1 = pk1 & 0xFFFFF;
        const float4* xp1 = (const float4*)(x + s1 * CCH) + lane * 2;
        float4 u0 = xp1[0], u1 = xp1[1];
        float d1 = qA.x*u0.x + qA.y*u0.y + qA.z*u0.z + qA.w*u0.w
                 + qB.x*u1.x + qB.y*u1.y + qB.z*u1.z + qB.w*u1.w;
#pragma unroll
        for (int o = 16; o >= 1; o >>= 1)
            d1 += __shfl_xor_sync(0xffffffffu, d1, o);
        float e1 = __expf(d1 + qbias + spdw[(pk1 >> 20) * 8 + h]);
        ssum += e1;
        float uu[8] = {u0.x,u0.y,u0.z,u0.w,u1.x,u1.y,u1.z,u1.w};
#pragma unroll
        for (int r = 0; r < 8; r++)
            acc[r] = fmaf(e1, uu[r], acc[r]);
    }

    float* P = g_pB + ((size_t)((d * NP + part) * HH + h)) * CCH + lane * 8;
    ((float4*)P)[0] = make_float4(acc[0], acc[1], acc[2], acc[3]);
    ((float4*)P)[1] = make_float4(acc[4], acc[5], acc[6], acc[7]);
    if (lane == 0) g_pS[(d * NP + part) * HH + h] = ssum;
}

// merge NP partials per dst, normalize per head, Wv epilogue
__global__ void __launch_bounds__(256) k_merge(const float* __restrict__ bv) {
    int d = blockIdx.x, t = threadIdx.x;
    __shared__ float Bs[HH * CCH];
    __shared__ float inv[HH];
    if (t < HH) {
        float s = 0.f;
#pragma unroll
        for (int pp = 0; pp < NP; pp++) s += g_pS[(d * NP + pp) * HH + t];
        inv[t] = (s > 0.f) ? (1.f / s) : 0.f;
    }
    __syncthreads();
#pragma unroll
    for (int e = t; e < HH * CCH; e += 256) {
        float s = 0.f;
#pragma unroll
        for (int pp = 0; pp < NP; pp++)
            s += g_pB[((size_t)(d * NP + pp)) * (HH * CCH) + e];
        Bs[e] = s * inv[e >> 8];
    }
    __syncthreads();
    int hh = t >> 5;
    float o = bv[t];
    const float* Bp = Bs + hh * CCH;
    const float* Wp = g_WvT + t;
#pragma unroll 4
    for (int k = 0; k < CCH; k++) o = fmaf(Wp[k * CCH], Bp[k], o);
    g_agg[d * CCH + t] = o;
}

// LayerNorm over v = agg + x (deg is constant per row -> cancels exactly)
__global__ void __launch_bounds__(256) k_ln(const float* __restrict__ x,
                                            const float* __restrict__ gamma,
                                            const float* __restrict__ beta,
                                            float* __restrict__ out) {
    int row  = blockIdx.x * 8 + (threadIdx.x >> 5);
    int lane = threadIdx.x & 31;
    if (row >= NN) return;
    const float4* xp = (const float4*)(x + (size_t)row * CCH) + lane * 2;
    float4 A = xp[0], B = xp[1];
    float v[8] = {A.x, A.y, A.z, A.w, B.x, B.y, B.z, B.w};
    if (row < ND) {
        const float4* ap = (const float4*)(g_agg + row * CCH) + lane * 2;
        float4 C = ap[0], D = ap[1];
        v[0] += C.x; v[1] += C.y; v[2] += C.z; v[3] += C.w;
        v[4] += D.x; v[5] += D.y; v[6] += D.z; v[7] += D.w;
    }
    float s = 0.f;
#pragma unroll
    for (int r = 0; r < 8; r++) s += v[r];
#pragma unroll
    for (int o = 16; o >= 1; o >>= 1) s += __shfl_xor_sync(0xffffffffu, s, o);
    float mu = s * (1.f / 256.f);
    float q = 0.f;
#pragma unroll
    for (int r = 0; r < 8; r++) { float tt = v[r] - mu; q += tt * tt; }
#pragma unroll
    for (int o = 16; o >= 1; o >>= 1) q += __shfl_xor_sync(0xffffffffu, q, o);
    float rs = rsqrtf(q * (1.f / 256.f) + 1e-5f);

    const float4* gp = (const float4*)gamma + lane * 2;
    const float4* bp = (const float4*)beta  + lane * 2;
    float4 G0 = gp[0], G1 = gp[1], B0 = bp[0], B1 = bp[1];
    float g[8]  = {G0.x,G0.y,G0.z,G0.w,G1.x,G1.y,G1.z,G1.w};
    float be[8] = {B0.x,B0.y,B0.z,B0.w,B1.x,B1.y,B1.z,B1.w};
    float r0[8];
#pragma unroll
    for (int r = 0; r < 8; r++) r0[r] = (v[r] - mu) * rs * g[r] + be[r];
    float4* op = (float4*)(out + (size_t)row * CCH) + lane * 2;
    op[0] = make_float4(r0[0], r0[1], r0[2], r0[3]);
    op[1] = make_float4(r0[4], r0[5], r0[6], r0[7]);
}

// ---------------- launch ----------------------------------------------------
extern "C" void kernel_launch(void* const* d_in, const int* in_sizes, int n_in,
                              void* d_out, int out_size) {
    const float* x     = (const float*)d_in[0];
    const int*   src   = (const int*)  d_in[1];
    const int*   dst   = (const int*)  d_in[2];
    const float* Wq    = (const float*)d_in[3];
    const float* bq    = (const float*)d_in[4];
    const float* Wk    = (const float*)d_in[5];
    const float* bk    = (const float*)d_in[6];
    const float* Wv    = (const float*)d_in[7];
    const float* bv    = (const float*)d_in[8];
    const float* spd_w = (const float*)d_in[9];
    const float* gamma = (const float*)d_in[10];
    const float* beta  = (const float*)d_in[11];
    float* out = (float*)d_out;
    (void)in_sizes; (void)n_in; (void)out_size;

    int eb = (EE + 255) / 256;
    k_zero<<<40, 256>>>();
    k_transpose<<<dim3(8, 8, 2), dim3(32, 32)>>>(Wq, Wv);
    k_prep<<<256, 256>>>(src, dst);
    k_scan<<<1, 256>>>();
    k_bfs<<<eb, 256>>>(src, dst, 2);
    k_bfs<<<eb, 256>>>(src, dst, 3);
    k_scatter<<<256, 256>>>(src, dst);
    k_qd<<<ND, 256>>>(x, bq);
    k_qt<<<ND, 256>>>(Wk, bk);
    k_main<<<ND * NP, 256>>>(x, spd_w);
    k_merge<<<ND, 256>>>(bv);
    k_ln<<<(NN + 7) / 8, 256>>>(x, gamma, beta, out);
}

// round 8
// speedup vs baseline: 2.3731x; 1.3452x over previous
#include <cuda_runtime.h>
#include <math.h>

#define NN 50000
#define EE 300000
#define CCH 256
#define HH 8
#define ND 256
#define NPW 16                   // warp-partials per dst in k_main
#define PADH 32                  // counter padding (ints) to spread L2 slices
#define FSCALE 0.17677669529663687f   // 1/sqrt(32)

typedef unsigned long long ull;

// ---------------- static device scratch (no runtime allocation) -------------
__device__ float    g_qt[ND*HH*CCH];     // per-(dst,head) query folded through Wk
__device__ float    g_qb[ND*HH];         // per-(dst,head) bias term
__device__ float    g_WqT[CCH*CCH];
__device__ float    g_WvT[CCH*CCH];
__device__ int      g_histP[ND*PADH];    // padded counters
__device__ int      g_offP[ND*PADH];
__device__ int      g_base[ND];
__device__ int      g_cnt[ND];
__device__ int      g_list[EE];          // edge ids with src < 256
__device__ int      g_nlist;
__device__ int      g_pack[EE];          // (spd<<20)|src, sorted by dst bucket
__device__ unsigned g_F1[ND*8];          // 256x256 bit frontier matrices
__device__ unsigned g_F2[ND*8];
__device__ unsigned g_F3[ND*8];
__device__ float    g_pB[(size_t)ND*NPW*HH*CCH];  // partial weighted-x sums
__device__ float    g_pS[ND*NPW*HH];     // partial exp-sums
__device__ float    g_agg[ND*CCH];       // attention output rows (incl. bv)

// ---------------- packed f32x2 helpers --------------------------------------
__device__ __forceinline__ ull ffma2(ull a, ull b, ull c) {
    ull d;
    asm("fma.rn.f32x2 %0, %1, %2, %3;" : "=l"(d) : "l"(a), "l"(b), "l"(c));
    return d;
}
__device__ __forceinline__ ull bcast2(float e) {
    ull r;
    asm("mov.b64 %0, {%1, %1};" : "=l"(r) : "f"(e));
    return r;
}
__device__ __forceinline__ float sum2(ull v) {
    float2 f;
    asm("mov.b64 {%0, %1}, %2;" : "=f"(f.x), "=f"(f.y) : "l"(v));
    return f.x + f.y;
}

union U8 { float4 f4[2]; ull u[4]; float f[8]; };

__device__ __forceinline__ void load8(U8& v, const float* p) {
    const float4* q = (const float4*)p;
    v.f4[0] = q[0];
    v.f4[1] = q[1];
}

// ---------------- fused init: zero scratch + transpose Wq/Wv ----------------
__global__ void __launch_bounds__(256) k_init(const float* __restrict__ Wq,
                                              const float* __restrict__ Wv) {
    __shared__ float tsm[32][33];
    int b = blockIdx.x;
    if (b < 40) {
        int i = b * 256 + threadIdx.x;
        if (i < ND*PADH) g_histP[i] = 0;
        if (i < ND*8) { g_F1[i] = 0u; g_F2[i] = 0u; g_F3[i] = 0u; }
        if (i == 0) g_nlist = 0;
    } else {
        int bb = b - 40;
        int z = bb >> 6, rem = bb & 63;
        int bx = rem & 7, by = rem >> 3;
        const float* W = z ? Wv : Wq;
        float*       O = z ? g_WvT : g_WqT;
        int tx = threadIdx.x & 31, ty0 = threadIdx.x >> 5;
#pragma unroll
        for (int j = 0; j < 4; j++) {
            int ty = ty0 + j * 8;
            tsm[ty][tx] = W[(by * 32 + ty) * CCH + bx * 32 + tx];
        }
        __syncthreads();
#pragma unroll
        for (int j = 0; j < 4; j++) {
            int ty = ty0 + j * 8;
            O[(bx * 32 + ty) * CCH + by * 32 + tx] = tsm[tx][ty];
        }
    }
}

// dst histogram via shared-memory aggregation; src<256 list; F1 seed
__global__ void __launch_bounds__(256) k_prep(const int* __restrict__ src,
                                              const int* __restrict__ dst) {
    __shared__ int sh[ND];
    int t = threadIdx.x;
    sh[t] = 0;
    __syncthreads();
    int chunk = (EE + gridDim.x - 1) / gridDim.x;
    int start = blockIdx.x * chunk;
    int end   = min(EE, start + chunk);
    for (int i = start + t; i < end; i += 256) {
        int d = dst[i], s = src[i];
        atomicAdd(&sh[d], 1);
        if (s < ND) {
            int p = atomicAdd(&g_nlist, 1);
            g_list[p] = i;
            atomicOr(&g_F1[d * 8 + (s >> 5)], 1u << (s & 31));
        }
    }
    __syncthreads();
    if (sh[t]) atomicAdd(&g_histP[t * PADH], sh[t]);
}

// fused: parallel exclusive scan + both BFS steps (single CTA)
__global__ void __launch_bounds__(256) k_mid(const int* __restrict__ src,
                                             const int* __restrict__ dst) {
    int t = threadIdx.x, lane = t & 31, w = t >> 5;
    int v = g_histP[t * PADH];
    int xs = v;
#pragma unroll
    for (int o = 1; o < 32; o <<= 1) {
        int y = __shfl_up_sync(0xffffffffu, xs, o);
        if (lane >= o) xs += y;
    }
    __shared__ int ws[8], wb[8];
    if (lane == 31) ws[w] = xs;
    __syncthreads();
    if (t == 0) { int a = 0; for (int i = 0; i < 8; i++) { wb[i] = a; a += ws[i]; } }
    __syncthreads();
    int excl = xs + wb[w] - v;
    g_base[t] = excl;
    g_cnt[t]  = v;
    g_offP[t * PADH] = excl;
    __syncthreads();

    int n = g_nlist;
    for (int i = t; i < n; i += 256) {
        int e = g_list[i];
        int s = src[e], dd = dst[e];
#pragma unroll
        for (int w2 = 0; w2 < 8; w2++) {
            unsigned vv = g_F1[s * 8 + w2];
            if (vv) atomicOr(&g_F2[dd * 8 + w2], vv);
        }
    }
    __threadfence();
    __syncthreads();
    for (int i = t; i < n; i += 256) {
        int e = g_list[i];
        int s = src[e], dd = dst[e];
#pragma unroll
        for (int w2 = 0; w2 < 8; w2++) {
            unsigned vv = __ldcg(&g_F2[s * 8 + w2]);
            if (vv) atomicOr(&g_F3[dd * 8 + w2], vv);
        }
    }
}

// counting-sort scatter (block-reserved ranges), packing (spd<<20)|src
__global__ void __launch_bounds__(256) k_scatter(const int* __restrict__ src,
                                                 const int* __restrict__ dst) {
    __shared__ int shCnt[ND];
    __shared__ int shBase[ND];
    int t = threadIdx.x;
    shCnt[t] = 0;
    __syncthreads();
    int chunk = (EE + gridDim.x - 1) / gridDim.x;
    int start = blockIdx.x * chunk;
    int end   = min(EE, start + chunk);
    for (int i = start + t; i < end; i += 256) atomicAdd(&shCnt[dst[i]], 1);
    __syncthreads();
    int c = shCnt[t];
    shBase[t] = c ? atomicAdd(&g_offP[t * PADH], c) : 0;
    __syncthreads();
    shCnt[t] = 0;
    __syncthreads();
    for (int i = start + t; i < end; i += 256) {
        int d = dst[i], s = src[i];
        int loc = atomicAdd(&shCnt[d], 1);
        int p = shBase[d] + loc;
        int spd = 4;
        if (s < ND) {
            unsigned msk = 1u << (d & 31);
            int w = d >> 5;
            if      (g_F1[s * 8 + w] & msk) spd = 1;
            else if (g_F2[s * 8 + w] & msk) spd = 2;
            else if (g_F3[s * 8 + w] & msk) spd = 3;
        }
        g_pack[p] = s | (spd << 20);
    }
}

// fused: Qd[d] = x[d]@Wq^T+bq (into smem), then qt/qb
__global__ void __launch_bounds__(256) k_qdqt(const float* __restrict__ x,
                                              const float* __restrict__ bq,
                                              const float* __restrict__ Wk,
                                              const float* __restrict__ bk) {
    int d = blockIdx.x, c = threadIdx.x;
    __shared__ float xs[CCH];
    __shared__ float qd[CCH];
    xs[c] = x[d * CCH + c];
    __syncthreads();
    float a = bq[c];
#pragma unroll 4
    for (int k = 0; k < CCH; k++) a = fmaf(xs[k], g_WqT[k * CCH + c], a);
    qd[c] = a;
    __syncthreads();
#pragma unroll
    for (int h = 0; h < HH; h++) {
        float acc = 0.f;
#pragma unroll 8
        for (int j = 0; j < 32; j++)
            acc = fmaf(qd[h * 32 + j], Wk[(h * 32 + j) * CCH + c], acc);
        g_qt[(d * HH + h) * CCH + c] = FSCALE * acc;
        if (c == 0) {
            float qb = 0.f;
            for (int j = 0; j < 32; j++) qb += qd[h * 32 + j] * bk[h * 32 + j];
            g_qb[d * HH + h] = FSCALE * qb;
        }
    }
}

// ---------------- main: warp-per-edge, all 8 heads per warp, f32x2 ----------
__global__ void __launch_bounds__(128, 2) k_main(const float* __restrict__ x,
                                                 const float* __restrict__ spd_w) {
    int d   = blockIdx.x >> 2;
    int cb  = blockIdx.x & 3;
    int tid = threadIdx.x;
    int wid = tid >> 5, lane = tid & 31;
    int part = cb * 4 + wid;           // 0..15

    __shared__ float spdw_s[40];
    __shared__ float qb_s[HH];
    if (tid < 40) spdw_s[tid] = spd_w[tid];
    if (tid < HH) qb_s[tid] = g_qb[d * HH + tid];
    __syncthreads();

    // per-thread qt for all 8 heads (channels lane*8 .. lane*8+7)
    ull q[HH][4];
#pragma unroll
    for (int h = 0; h < HH; h++) {
        U8 qv;
        load8(qv, g_qt + (d * HH + h) * CCH + lane * 8);
#pragma unroll
        for (int i = 0; i < 4; i++) q[h][i] = qv.u[i];
    }

    int b16i = (lane >> 4) & 1, b8i = (lane >> 3) & 1, b4i = (lane >> 2) & 1;
    bool b16 = b16i, b8 = b8i, b4 = b4i;
    int myh = (b16i << 2) | (b8i << 1) | b4i;
    float myqb = qb_s[myh];

    ull acc[HH][4];
#pragma unroll
    for (int h = 0; h < HH; h++)
#pragma unroll
        for (int i = 0; i < 4; i++) acc[h][i] = 0ull;

    float ss = 0.f;

    int b0 = g_base[d], cnt = g_cnt[d];
    int pend = b0 + cnt;
    int p = b0 + part;
    if (p < pend) {
        int pclamp = pend - 1;
        int pk0 = g_pack[p];
        int pk1 = g_pack[min(p + NPW, pclamp)];
        U8 xv;
        load8(xv, x + (size_t)(pk0 & 0xFFFFF) * CCH + lane * 8);

        while (p < pend) {
            int pn = p + NPW;
            int pk2 = g_pack[min(pn + NPW, pclamp)];
            U8 xn;
            load8(xn, x + (size_t)(pk1 & 0xFFFFF) * CCH + lane * 8);

            // --- dots for 8 heads (f32x2) ---
            float v[8];
#pragma unroll
            for (int h = 0; h < HH; h++) {
                ull dp = 0ull;
#pragma unroll
                for (int i = 0; i < 4; i++) dp = ffma2(q[h][i], xv.u[i], dp);
                v[h] = sum2(dp);
            }

            // --- reduce-scatter: 8 head sums across 32 lanes ---
            float k0 = b16 ? v[4] : v[0], s0 = b16 ? v[0] : v[4];
            float k1 = b16 ? v[5] : v[1], s1 = b16 ? v[1] : v[5];
            float k2 = b16 ? v[6] : v[2], s2 = b16 ? v[2] : v[6];
            float k3 = b16 ? v[7] : v[3], s3 = b16 ? v[3] : v[7];
            k0 += __shfl_xor_sync(0xffffffffu, s0, 16);
            k1 += __shfl_xor_sync(0xffffffffu, s1, 16);
            k2 += __shfl_xor_sync(0xffffffffu, s2, 16);
            k3 += __shfl_xor_sync(0xffffffffu, s3, 16);
            float m0 = b8 ? k2 : k0, t0 = b8 ? k0 : k2;
            float m1 = b8 ? k3 : k1, t1 = b8 ? k1 : k3;
            m0 += __shfl_xor_sync(0xffffffffu, t0, 8);
            m1 += __shfl_xor_sync(0xffffffffu, t1, 8);
            float n0 = b4 ? m1 : m0, u0 = b4 ? m0 : m1;
            n0 += __shfl_xor_sync(0xffffffffu, u0, 4);
            n0 += __shfl_xor_sync(0xffffffffu, n0, 2);
            n0 += __shfl_xor_sync(0xffffffffu, n0, 1);

            // --- score + exp for my head ---
            int spd = pk0 >> 20;
            float e = __expf(n0 + myqb + spdw_s[spd * 8 + myh]);
            ss += e;

            // --- broadcast weights, accumulate B (f32x2) ---
#pragma unroll
            for (int h = 0; h < HH; h++) {
                float eh = __shfl_sync(0xffffffffu, e, h * 4);
                ull e2 = bcast2(eh);
#pragma unroll
                for (int i = 0; i < 4; i++)
                    acc[h][i] = ffma2(e2, xv.u[i], acc[h][i]);
            }

            pk0 = pk1; pk1 = pk2; xv = xn;
            p = pn;
        }
    }

    // write per-warp partials (unique slot -> plain stores)
    float* P = g_pB + (size_t)(d * NPW + part) * (HH * CCH) + lane * 8;
#pragma unroll
    for (int h = 0; h < HH; h++) {
        U8 tmp;
#pragma unroll
        for (int i = 0; i < 4; i++) tmp.u[i] = acc[h][i];
        float4* dst4 = (float4*)(P + h * CCH);
        dst4[0] = tmp.f4[0];
        dst4[1] = tmp.f4[1];
    }
    if ((lane & 3) == 0) g_pS[(d * NPW + part) * HH + myh] = ss;
}

// merge NPW partials per dst, normalize per head, Wv epilogue
__global__ void __launch_bounds__(256) k_merge(const float* __restrict__ bv) {
    int d = blockIdx.x, t = threadIdx.x;
    __shared__ float Bs[HH * CCH];
    __shared__ float inv[HH];
    if (t < HH) {
        float s = 0.f;
#pragma unroll
        for (int pp = 0; pp < NPW; pp++) s += g_pS[(d * NPW + pp) * HH + t];
        inv[t] = (s > 0.f) ? (1.f / s) : 0.f;
    }
    __syncthreads();
#pragma unroll
    for (int e = t; e < HH * CCH; e += 256) {
        float s = 0.f;
#pragma unroll
        for (int pp = 0; pp < NPW; pp++)
            s += g_pB[(size_t)(d * NPW + pp) * (HH * CCH) + e];
        Bs[e] = s * inv[e >> 8];
    }
    __syncthreads();
    int hh = t >> 5;
    float o = bv[t];
    const float* Bp = Bs + hh * CCH;
    const float* Wp = g_WvT + t;
#pragma unroll 4
    for (int k = 0; k < CCH; k++) o = fmaf(Wp[k * CCH], Bp[k], o);
    g_agg[d * CCH + t] = o;
}

// LayerNorm over v = agg + x (deg constant per row -> cancels exactly)
__global__ void __launch_bounds__(256) k_ln(const float* __restrict__ x,
                                            const float* __restrict__ gamma,
                                            const float* __restrict__ beta,
                                            float* __restrict__ out) {
    int row  = blockIdx.x * 8 + (threadIdx.x >> 5);
    int lane = threadIdx.x & 31;
    if (row >= NN) return;
    const float4* xp = (const float4*)(x + (size_t)row * CCH) + lane * 2;
    float4 A = xp[0], B = xp[1];
    float v[8] = {A.x, A.y, A.z, A.w, B.x, B.y, B.z, B.w};
    if (row < ND) {
        const float4* ap = (const float4*)(g_agg + row * CCH) + lane * 2;
        float4 C = ap[0], D = ap[1];
        v[0] += C.x; v[1] += C.y; v[2] += C.z; v[3] += C.w;
        v[4] += D.x; v[5] += D.y; v[6] += D.z; v[7] += D.w;
    }
    float s = 0.f;
#pragma unroll
    for (int r = 0; r < 8; r++) s += v[r];
#pragma unroll
    for (int o = 16; o >= 1; o >>= 1) s += __shfl_xor_sync(0xffffffffu, s, o);
    float mu = s * (1.f / 256.f);
    float q = 0.f;
#pragma unroll
    for (int r = 0; r < 8; r++) { float tt = v[r] - mu; q += tt * tt; }
#pragma unroll
    for (int o = 16; o >= 1; o >>= 1) q += __shfl_xor_sync(0xffffffffu, q, o);
    float rs = rsqrtf(q * (1.f / 256.f) + 1e-5f);

    const float4* gp = (const float4*)gamma + lane * 2;
    const float4* bp = (const float4*)beta  + lane * 2;
    float4 G0 = gp[0], G1 = gp[1], B0 = bp[0], B1 = bp[1];
    float g[8]  = {G0.x,G0.y,G0.z,G0.w,G1.x,G1.y,G1.z,G1.w};
    float be[8] = {B0.x,B0.y,B0.z,B0.w,B1.x,B1.y,B1.z,B1.w};
    float r0[8];
#pragma unroll
    for (int r = 0; r < 8; r++) r0[r] = (v[r] - mu) * rs * g[r] + be[r];
    float4* op = (float4*)(out + (size_t)row * CCH) + lane * 2;
    op[0] = make_float4(r0[0], r0[1], r0[2], r0[3]);
    op[1] = make_float4(r0[4], r0[5], r0[6], r0[7]);
}

// ---------------- launch ----------------------------------------------------
extern "C" void kernel_launch(void* const* d_in, const int* in_sizes, int n_in,
                              void* d_out, int out_size) {
    const float* x     = (const float*)d_in[0];
    const int*   src   = (const int*)  d_in[1];
    const int*   dst   = (const int*)  d_in[2];
    const float* Wq    = (const float*)d_in[3];
    const float* bq    = (const float*)d_in[4];
    const float* Wk    = (const float*)d_in[5];
    const float* bk    = (const float*)d_in[6];
    const float* Wv    = (const float*)d_in[7];
    const float* bv    = (const float*)d_in[8];
    const float* spd_w = (const float*)d_in[9];
    const float* gamma = (const float*)d_in[10];
    const float* beta  = (const float*)d_in[11];
    float* out = (float*)d_out;
    (void)in_sizes; (void)n_in; (void)out_size;

    k_init<<<168, 256>>>(Wq, Wv);
    k_prep<<<256, 256>>>(src, dst);
    k_mid<<<1, 256>>>(src, dst);
    k_scatter<<<256, 256>>>(src, dst);
    k_qdqt<<<ND, 256>>>(x, bq, Wk, bk);
    k_main<<<ND * 4, 128>>>(x, spd_w);
    k_merge<<<ND, 256>>>(bv);
    k_ln<<<(NN + 7) / 8, 256>>>(x, gamma, beta, out);
}

// round 10
// speedup vs baseline: 2.4265x; 1.0225x over previous
#include <cuda_runtime.h>
#include <math.h>

#define NN 50000
#define EE 300000
#define CCH 256
#define HH 8
#define ND 256
#define NPW 16                   // warp-partials per dst in k_main
#define PADH 32                  // counter padding (ints) to spread L2 slices
#define ST 8                     // cp.async ring stages per warp
#define CAPW 128                 // smem pack-cache entries per warp
#define FSCALE 0.17677669529663687f   // 1/sqrt(32)

typedef unsigned long long ull;

// ---------------- static device scratch (no runtime allocation) -------------
__device__ float    g_qt[ND*HH*CCH];     // per-(dst,head) query folded through Wk
__device__ float    g_qb[ND*HH];         // per-(dst,head) bias term
__device__ float    g_WqT[CCH*CCH];
__device__ float    g_WvT[CCH*CCH];
__device__ int      g_histP[ND*PADH];    // padded counters
__device__ int      g_offP[ND*PADH];
__device__ int      g_base[ND];
__device__ int      g_cnt[ND];
__device__ int      g_list[EE];          // edge ids with src < 256
__device__ int      g_nlist;
__device__ int      g_pack[EE];          // (spd<<20)|src, sorted by dst bucket
__device__ unsigned g_F1[ND*8];          // 256x256 bit frontier matrices
__device__ unsigned g_F2[ND*8];
__device__ unsigned g_F3[ND*8];
__device__ float    g_pB[(size_t)ND*NPW*HH*CCH];  // partial weighted-x sums
__device__ float    g_pS[ND*NPW*HH];     // partial exp-sums
__device__ float    g_agg[ND*CCH];       // attention output rows (incl. bv)

// ---------------- packed f32x2 + cp.async helpers ---------------------------
__device__ __forceinline__ ull ffma2(ull a, ull b, ull c) {
    ull d;
    asm("fma.rn.f32x2 %0, %1, %2, %3;" : "=l"(d) : "l"(a), "l"(b), "l"(c));
    return d;
}
__device__ __forceinline__ ull bcast2(float e) {
    ull r;
    asm("mov.b64 %0, {%1, %1};" : "=l"(r) : "f"(e));
    return r;
}
__device__ __forceinline__ float sum2(ull v) {
    float2 f;
    asm("mov.b64 {%0, %1}, %2;" : "=f"(f.x), "=f"(f.y) : "l"(v));
    return f.x + f.y;
}
__device__ __forceinline__ void cpasync16(unsigned s, const void* g) {
    asm volatile("cp.async.cg.shared.global [%0], [%1], 16;" :: "r"(s), "l"(g));
}
#define CP_COMMIT() asm volatile("cp.async.commit_group;")
#define CP_WAIT(n)  asm volatile("cp.async.wait_group %0;" :: "n"(n))

union U8 { float4 f4[2]; ull u[4]; float f[8]; };

__device__ __forceinline__ void load8(U8& v, const float* p) {
    const float4* q = (const float4*)p;
    v.f4[0] = q[0];
    v.f4[1] = q[1];
}

// per-edge compute: dots (8 heads, f32x2), reduce-scatter shfl tree, exp,
// weighted accumulation.
__device__ __forceinline__ void edge_compute(
    const U8& xv, int pk, const ull (&q)[HH][4], ull (&acc)[HH][4],
    float& ss, const float* spdw_s, float myqb, int myh,
    bool b16, bool b8, bool b4)
{
    float v[8];
#pragma unroll
    for (int h = 0; h < HH; h++) {
        ull dp = 0ull;
#pragma unroll
        for (int i = 0; i < 4; i++) dp = ffma2(q[h][i], xv.u[i], dp);
        v[h] = sum2(dp);
    }
    float k0 = b16 ? v[4] : v[0], s0 = b16 ? v[0] : v[4];
    float k1 = b16 ? v[5] : v[1], s1 = b16 ? v[1] : v[5];
    float k2 = b16 ? v[6] : v[2], s2 = b16 ? v[2] : v[6];
    float k3 = b16 ? v[7] : v[3], s3 = b16 ? v[3] : v[7];
    k0 += __shfl_xor_sync(0xffffffffu, s0, 16);
    k1 += __shfl_xor_sync(0xffffffffu, s1, 16);
    k2 += __shfl_xor_sync(0xffffffffu, s2, 16);
    k3 += __shfl_xor_sync(0xffffffffu, s3, 16);
    float m0 = b8 ? k2 : k0, t0 = b8 ? k0 : k2;
    float m1 = b8 ? k3 : k1, t1 = b8 ? k1 : k3;
    m0 += __shfl_xor_sync(0xffffffffu, t0, 8);
    m1 += __shfl_xor_sync(0xffffffffu, t1, 8);
    float n0 = b4 ? m1 : m0, u0 = b4 ? m0 : m1;
    n0 += __shfl_xor_sync(0xffffffffu, u0, 4);
    n0 += __shfl_xor_sync(0xffffffffu, n0, 2);
    n0 += __shfl_xor_sync(0xffffffffu, n0, 1);

    int spd = pk >> 20;
    float e = __expf(n0 + myqb + spdw_s[spd * 8 + myh]);
    ss += e;

#pragma unroll
    for (int h = 0; h < HH; h++) {
        float eh = __shfl_sync(0xffffffffu, e, h * 4);
        ull e2 = bcast2(eh);
#pragma unroll
        for (int i = 0; i < 4; i++)
            acc[h][i] = ffma2(e2, xv.u[i], acc[h][i]);
    }
}

// ---------------- fused init: zero scratch + transpose Wq/Wv ----------------
__global__ void __launch_bounds__(256) k_init(const float* __restrict__ Wq,
                                              const float* __restrict__ Wv) {
    __shared__ float tsm[32][33];
    int b = blockIdx.x;
    if (b < 40) {
        int i = b * 256 + threadIdx.x;
        if (i < ND*PADH) g_histP[i] = 0;
        if (i < ND*8) { g_F1[i] = 0u; g_F2[i] = 0u; g_F3[i] = 0u; }
        if (i == 0) g_nlist = 0;
    } else {
        int bb = b - 40;
        int z = bb >> 6, rem = bb & 63;
        int bx = rem & 7, by = rem >> 3;
        const float* W = z ? Wv : Wq;
        float*       O = z ? g_WvT : g_WqT;
        int tx = threadIdx.x & 31, ty0 = threadIdx.x >> 5;
#pragma unroll
        for (int j = 0; j < 4; j++) {
            int ty = ty0 + j * 8;
            tsm[ty][tx] = W[(by * 32 + ty) * CCH + bx * 32 + tx];
        }
        __syncthreads();
#pragma unroll
        for (int j = 0; j < 4; j++) {
            int ty = ty0 + j * 8;
            O[(bx * 32 + ty) * CCH + by * 32 + tx] = tsm[tx][ty];
        }
    }
}

// dst histogram via shared-memory aggregation; src<256 list; F1 seed
__global__ void __launch_bounds__(256) k_prep(const int* __restrict__ src,
                                              const int* __restrict__ dst) {
    __shared__ int sh[ND];
    int t = threadIdx.x;
    sh[t] = 0;
    __syncthreads();
    int chunk = (EE + gridDim.x - 1) / gridDim.x;
    int start = blockIdx.x * chunk;
    int end   = min(EE, start + chunk);
    for (int i = start + t; i < end; i += 256) {
        int d = dst[i], s = src[i];
        atomicAdd(&sh[d], 1);
        if (s < ND) {
            int p = atomicAdd(&g_nlist, 1);
            g_list[p] = i;
            atomicOr(&g_F1[d * 8 + (s >> 5)], 1u << (s & 31));
        }
    }
    __syncthreads();
    if (sh[t]) atomicAdd(&g_histP[t * PADH], sh[t]);
}

// fused: parallel exclusive scan + both BFS steps (single CTA)
__global__ void __launch_bounds__(256) k_mid(const int* __restrict__ src,
                                             const int* __restrict__ dst) {
    int t = threadIdx.x, lane = t & 31, w = t >> 5;
    int v = g_histP[t * PADH];
    int xs = v;
#pragma unroll
    for (int o = 1; o < 32; o <<= 1) {
        int y = __shfl_up_sync(0xffffffffu, xs, o);
        if (lane >= o) xs += y;
    }
    __shared__ int ws[8], wb[8];
    if (lane == 31) ws[w] = xs;
    __syncthreads();
    if (t == 0) { int a = 0; for (int i = 0; i < 8; i++) { wb[i] = a; a += ws[i]; } }
    __syncthreads();
    int excl = xs + wb[w] - v;
    g_base[t] = excl;
    g_cnt[t]  = v;
    g_offP[t * PADH] = excl;
    __syncthreads();

    int n = g_nlist;
    for (int i = t; i < n; i += 256) {
        int e = g_list[i];
        int s = src[e], dd = dst[e];
#pragma unroll
        for (int w2 = 0; w2 < 8; w2++) {
            unsigned vv = g_F1[s * 8 + w2];
            if (vv) atomicOr(&g_F2[dd * 8 + w2], vv);
        }
    }
    __threadfence();
    __syncthreads();
    for (int i = t; i < n; i += 256) {
        int e = g_list[i];
        int s = src[e], dd = dst[e];
#pragma unroll
        for (int w2 = 0; w2 < 8; w2++) {
            unsigned vv = __ldcg(&g_F2[s * 8 + w2]);
            if (vv) atomicOr(&g_F3[dd * 8 + w2], vv);
        }
    }
}

// counting-sort scatter (block-reserved ranges), packing (spd<<20)|src
__global__ void __launch_bounds__(256) k_scatter(const int* __restrict__ src,
                                                 const int* __restrict__ dst) {
    __shared__ int shCnt[ND];
    __shared__ int shBase[ND];
    int t = threadIdx.x;
    shCnt[t] = 0;
    __syncthreads();
    int chunk = (EE + gridDim.x - 1) / gridDim.x;
    int start = blockIdx.x * chunk;
    int end   = min(EE, start + chunk);
    for (int i = start + t; i < end; i += 256) atomicAdd(&shCnt[dst[i]], 1);
    __syncthreads();
    int c = shCnt[t];
    shBase[t] = c ? atomicAdd(&g_offP[t * PADH], c) : 0;
    __syncthreads();
    shCnt[t] = 0;
    __syncthreads();
    for (int i = start + t; i < end; i += 256) {
        int d = dst[i], s = src[i];
        int loc = atomicAdd(&shCnt[d], 1);
        int p = shBase[d] + loc;
        int spd = 4;
        if (s < ND) {
            unsigned msk = 1u << (d & 31);
            int w = d >> 5;
            if      (g_F1[s * 8 + w] & msk) spd = 1;
            else if (g_F2[s * 8 + w] & msk) spd = 2;
            else if (g_F3[s * 8 + w] & msk) spd = 3;
        }
        g_pack[p] = s | (spd << 20);
    }
}

// fused: Qd[d] = x[d]@Wq^T+bq (into smem), then qt/qb
__global__ void __launch_bounds__(256) k_qdqt(const float* __restrict__ x,
                                              const float* __restrict__ bq,
                                              const float* __restrict__ Wk,
                                              const float* __restrict__ bk) {
    int d = blockIdx.x, c = threadIdx.x;
    __shared__ float xs[CCH];
    __shared__ float qd[CCH];
    xs[c] = x[d * CCH + c];
    __syncthreads();
    float a = bq[c];
#pragma unroll 4
    for (int k = 0; k < CCH; k++) a = fmaf(xs[k], g_WqT[k * CCH + c], a);
    qd[c] = a;
    __syncthreads();
#pragma unroll
    for (int h = 0; h < HH; h++) {
        float acc = 0.f;
#pragma unroll 8
        for (int j = 0; j < 32; j++)
            acc = fmaf(qd[h * 32 + j], Wk[(h * 32 + j) * CCH + c], acc);
        g_qt[(d * HH + h) * CCH + c] = FSCALE * acc;
        if (c == 0) {
            float qb = 0.f;
            for (int j = 0; j < 32; j++) qb += qd[h * 32 + j] * bk[h * 32 + j];
            g_qb[d * HH + h] = FSCALE * qb;
        }
    }
}

// ---------------- main: warp-per-edge, cp.async x pipeline ------------------
__global__ void __launch_bounds__(128, 2) k_main(const float* __restrict__ x,
                                                 const float* __restrict__ spd_w) {
    int d   = blockIdx.x >> 2;
    int cb  = blockIdx.x & 3;
    int tid = threadIdx.x;
    int wid = tid >> 5, lane = tid & 31;
    int part = cb * 4 + wid;           // 0..15

    __shared__ float xring[4][ST][CCH];   // 32 KB: per-warp cp.async rings
    __shared__ int   pks[4][CAPW];        // per-warp pack cache
    __shared__ float spdw_s[40];
    __shared__ float qb_s[HH];
    if (tid < 40) spdw_s[tid] = spd_w[tid];
    if (tid < HH) qb_s[tid] = g_qb[d * HH + tid];
    __syncthreads();

    // per-thread qt for all 8 heads (channels lane*8 .. lane*8+7)
    ull q[HH][4];
#pragma unroll
    for (int h = 0; h < HH; h++) {
        U8 qv;
        load8(qv, g_qt + (d * HH + h) * CCH + lane * 8);
#pragma unroll
        for (int i = 0; i < 4; i++) q[h][i] = qv.u[i];
    }

    int b16i = (lane >> 4) & 1, b8i = (lane >> 3) & 1, b4i = (lane >> 2) & 1;
    bool b16 = b16i, b8 = b8i, b4 = b4i;
    int myh = (b16i << 2) | (b8i << 1) | b4i;
    float myqb = qb_s[myh];

    ull acc[HH][4];
#pragma unroll
    for (int h = 0; h < HH; h++)
#pragma unroll
        for (int i = 0; i < 4; i++) acc[h][i] = 0ull;
    float ss = 0.f;

    // contiguous chunk for this partial
    int b0 = g_base[d], cnt = g_cnt[d];
    int per = (cnt + NPW - 1) >> 4;
    int a   = b0 + part * per;
    int bnd = min(b0 + cnt, a + per);
    int n   = max(0, bnd - a);
    int nc  = min(n, CAPW);

    // cache pack words for this warp's chunk
    for (int j = lane; j < nc; j += 32) pks[wid][j] = g_pack[a + j];
    __syncwarp();

    unsigned sbase = (unsigned)__cvta_generic_to_shared(&xring[wid][0][0]) + lane * 32u;

    // prologue: ST-1 stages in flight
#pragma unroll
    for (int j = 0; j < ST - 1; j++) {
        if (j < nc) {
            int pk = pks[wid][j];
            const float* gp = x + (size_t)(pk & 0xFFFFF) * CCH + lane * 8;
            unsigned sa = sbase + (unsigned)(j & (ST - 1)) * (CCH * 4);
            cpasync16(sa, gp);
            cpasync16(sa + 16, gp + 4);
        }
        CP_COMMIT();
    }

    for (int i = 0; i < nc; i++) {
        CP_WAIT(ST - 2);
        U8 xv;
        {
            const float4* sp = (const float4*)&xring[wid][i & (ST - 1)][lane * 8];
            xv.f4[0] = sp[0];
            xv.f4[1] = sp[1];
        }
        int pk = pks[wid][i];
        edge_compute(xv, pk, q, acc, ss, spdw_s, myqb, myh, b16, b8, b4);
        int j = i + (ST - 1);
        if (j < nc) {
            int pk2 = pks[wid][j];
            const float* gp = x + (size_t)(pk2 & 0xFFFFF) * CCH + lane * 8;
            unsigned sa = sbase + (unsigned)(j & (ST - 1)) * (CCH * 4);
            cpasync16(sa, gp);
            cpasync16(sa + 16, gp + 4);
        }
        CP_COMMIT();
    }
    CP_WAIT(0);

    // fallback for (statistically impossible) oversized chunks
    for (int i = nc; i < n; i++) {
        int pk = g_pack[a + i];
        U8 xv;
        load8(xv, x + (size_t)(pk & 0xFFFFF) * CCH + lane * 8);
        edge_compute(xv, pk, q, acc, ss, spdw_s, myqb, myh, b16, b8, b4);
    }

    // write per-warp partials (unique slot -> plain stores)
    float* P = g_pB + (size_t)(d * NPW + part) * (HH * CCH) + lane * 8;
#pragma unroll
    for (int h = 0; h < HH; h++) {
        U8 tmp;
#pragma unroll
        for (int i = 0; i < 4; i++) tmp.u[i] = acc[h][i];
        float4* dst4 = (float4*)(P + h * CCH);
        dst4[0] = tmp.f4[0];
        dst4[1] = tmp.f4[1];
    }
    if ((lane & 3) == 0) g_pS[(d * NPW + part) * HH + myh] = ss;
}

// merge NPW partials per dst, normalize per head, Wv epilogue
__global__ void __launch_bounds__(256) k_merge(const float* __restrict__ bv) {
    int d = blockIdx.x, t = threadIdx.x;
    __shared__ float Bs[HH * CCH];
    __shared__ float inv[HH];
    if (t < HH) {
        float s = 0.f;
#pragma unroll
        for (int pp = 0; pp < NPW; pp++) s += g_pS[(d * NPW + pp) * HH + t];
        inv[t] = (s > 0.f) ? (1.f / s) : 0.f;
    }
    __syncthreads();
#pragma unroll
    for (int e = t; e < HH * CCH; e += 256) {
        float s = 0.f;
#pragma unroll
        for (int pp = 0; pp < NPW; pp++)
            s += g_pB[(size_t)(d * NPW + pp) * (HH * CCH) + e];
        Bs[e] = s * inv[e >> 8];
    }
    __syncthreads();
    int hh = t >> 5;
    float o = bv[t];
    const float* Bp = Bs + hh * CCH;
    const float* Wp = g_WvT + t;
#pragma unroll 4
    for (int k = 0; k < CCH; k++) o = fmaf(Wp[k * CCH], Bp[k], o);
    g_agg[d * CCH + t] = o;
}

// LayerNorm over v = agg + x (deg constant per row -> cancels exactly)
__global__ void __launch_bounds__(256) k_ln(const float* __restrict__ x,
                                            const float* __restrict__ gamma,
                                            const float* __restrict__ beta,
                                            float* __restrict__ out) {
    int row  = blockIdx.x * 8 + (threadIdx.x >> 5);
    int lane = threadIdx.x & 31;
    if (row >= NN) return;
    const float4* xp = (const float4*)(x + (size_t)row * CCH) + lane * 2;
    float4 A = xp[0], B = xp[1];
    float v[8] = {A.x, A.y, A.z, A.w, B.x, B.y, B.z, B.w};
    if (row < ND) {
        const float4* ap = (const float4*)(g_agg + row * CCH) + lane * 2;
        float4 C = ap[0], D = ap[1];
        v[0] += C.x; v[1] += C.y; v[2] += C.z; v[3] += C.w;
        v[4] += D.x; v[5] += D.y; v[6] += D.z; v[7] += D.w;
    }
    float s = 0.f;
#pragma unroll
    for (int r = 0; r < 8; r++) s += v[r];
#pragma unroll
    for (int o = 16; o >= 1; o >>= 1) s += __shfl_xor_sync(0xffffffffu, s, o);
    float mu = s * (1.f / 256.f);
    float q = 0.f;
#pragma unroll
    for (int r = 0; r < 8; r++) { float tt = v[r] - mu; q += tt * tt; }
#pragma unroll
    for (int o = 16; o >= 1; o >>= 1) q += __shfl_xor_sync(0xffffffffu, q, o);
    float rs = rsqrtf(q * (1.f / 256.f) + 1e-5f);

    const float4* gp = (const float4*)gamma + lane * 2;
    const float4* bp = (const float4*)beta  + lane * 2;
    float4 G0 = gp[0], G1 = gp[1], B0 = bp[0], B1 = bp[1];
    float g[8]  = {G0.x,G0.y,G0.z,G0.w,G1.x,G1.y,G1.z,G1.w};
    float be[8] = {B0.x,B0.y,B0.z,B0.w,B1.x,B1.y,B1.z,B1.w};
    float r0[8];
#pragma unroll
    for (int r = 0; r < 8; r++) r0[r] = (v[r] - mu) * rs * g[r] + be[r];
    float4* op = (float4*)(out + (size_t)row * CCH) + lane * 2;
    op[0] = make_float4(r0[0], r0[1], r0[2], r0[3]);
    op[1] = make_float4(r0[4], r0[5], r0[6], r0[7]);
}

// ---------------- launch ----------------------------------------------------
extern "C" void kernel_launch(void* const* d_in, const int* in_sizes, int n_in,
                              void* d_out, int out_size) {
    const float* x     = (const float*)d_in[0];
    const int*   src   = (const int*)  d_in[1];
    const int*   dst   = (const int*)  d_in[2];
    const float* Wq    = (const float*)d_in[3];
    const float* bq    = (const float*)d_in[4];
    const float* Wk    = (const float*)d_in[5];
    const float* bk    = (const float*)d_in[6];
    const float* Wv    = (const float*)d_in[7];
    const float* bv    = (const float*)d_in[8];
    const float* spd_w = (const float*)d_in[9];
    const float* gamma = (const float*)d_in[10];
    const float* beta  = (const float*)d_in[11];
    float* out = (float*)d_out;
    (void)in_sizes; (void)n_in; (void)out_size;

    k_init<<<168, 256>>>(Wq, Wv);
    k_prep<<<256, 256>>>(src, dst);
    k_mid<<<1, 256>>>(src, dst);
    k_scatter<<<256, 256>>>(src, dst);
    k_qdqt<<<ND, 256>>>(x, bq, Wk, bk);
    k_main<<<ND * 4, 128>>>(x, spd_w);
    k_merge<<<ND, 256>>>(bv);
    k_ln<<<(NN + 7) / 8, 256>>>(x, gamma, beta, out);
}

// round 11
// speedup vs baseline: 2.6388x; 1.0875x over previous
#include <cuda_runtime.h>
#include <math.h>

#define NN 50000
#define EE 300000
#define CCH 256
#define HH 8
#define ND 256
#define NPW 16                   // warp-partials per dst in k_main
#define PADH 32                  // counter padding (ints) to spread L2 slices
#define CAPW 128                 // smem pack-cache entries per warp
#define ROWF 288                 // padded floats per edge row in smem ring
#define FSCALE 0.17677669529663687f   // 1/sqrt(32)

typedef unsigned long long ull;

// ---------------- static device scratch (no runtime allocation) -------------
__device__ float    g_qt[ND*HH*CCH];     // per-(dst,head) query folded through Wk
__device__ float    g_qb[ND*HH];         // per-(dst,head) bias term
__device__ float    g_WqT[CCH*CCH];
__device__ float    g_WvT[CCH*CCH];
__device__ int      g_histP[ND*PADH];    // padded counters
__device__ int      g_offP[ND*PADH];
__device__ int      g_base[ND];
__device__ int      g_cnt[ND];
__device__ int      g_list[EE];          // edge ids with src < 256
__device__ int      g_nlist;
__device__ int      g_pack[EE];          // (spd<<20)|src, sorted by dst bucket
__device__ unsigned g_F1[ND*8];          // 256x256 bit frontier matrices
__device__ unsigned g_F2[ND*8];
__device__ unsigned g_F3[ND*8];
__device__ float    g_pB[(size_t)ND*NPW*HH*CCH];  // partial weighted-x sums
__device__ float    g_pS[ND*NPW*HH];     // partial exp-sums
__device__ float    g_agg[ND*CCH];       // attention output rows (incl. bv)

// ---------------- packed f32x2 + cp.async helpers ---------------------------
__device__ __forceinline__ ull ffma2(ull a, ull b, ull c) {
    ull d;
    asm("fma.rn.f32x2 %0, %1, %2, %3;" : "=l"(d) : "l"(a), "l"(b), "l"(c));
    return d;
}
__device__ __forceinline__ ull bcast2(float e) {
    ull r;
    asm("mov.b64 %0, {%1, %1};" : "=l"(r) : "f"(e));
    return r;
}
__device__ __forceinline__ float sum2(ull v) {
    float2 f;
    asm("mov.b64 {%0, %1}, %2;" : "=f"(f.x), "=f"(f.y) : "l"(v));
    return f.x + f.y;
}
__device__ __forceinline__ void cpasync16(unsigned s, const void* g) {
    asm volatile("cp.async.cg.shared.global [%0], [%1], 16;" :: "r"(s), "l"(g));
}
#define CP_COMMIT() asm volatile("cp.async.commit_group;")
#define CP_WAIT(n)  asm volatile("cp.async.wait_group %0;" :: "n"(n))

union U8 { float4 f4[2]; ull u[4]; float f[8]; };

__device__ __forceinline__ void load8(U8& v, const float* p) {
    const float4* q = (const float4*)p;
    v.f4[0] = q[0];
    v.f4[1] = q[1];
}

// bank-swizzled byte offset of a lane's 32B slot within one edge row
__device__ __forceinline__ unsigned slot_off(int lane) {
    return (unsigned)(lane * 32 + ((lane >> 2) & 7) * 16);
}

// 4-edge batched compute: dots for 32 (edge,head) combos, one butterfly
// reduce-scatter (lane L ends with combo L), one exp, weighted accumulation.
__device__ __forceinline__ void batch_compute(
    const U8 (&xv)[4], int pkl, bool val,
    const ull (&q)[HH][4], ull (&acc)[HH][4], float& ss,
    const float* spdw_s, const float* qb_s, int lane)
{
    float r[32];
#pragma unroll
    for (int ed = 0; ed < 4; ed++) {
#pragma unroll
        for (int h = 0; h < HH; h++) {
            ull dp = 0ull;
#pragma unroll
            for (int i = 0; i < 4; i++) dp = ffma2(q[h][i], xv[ed].u[i], dp);
            r[ed * 8 + h] = sum2(dp);
        }
    }
    // butterfly reduce-scatter across 32 lanes / 32 combos
#pragma unroll
    for (int lev = 0; lev < 5; lev++) {
        const int o  = 16 >> lev;
        const int nv = 16 >> lev;
        bool hi = (lane & o) != 0;
#pragma unroll
        for (int i = 0; i < 16; i++) {
            if (i < nv) {
                float keep = hi ? r[i + nv] : r[i];
                float send = hi ? r[i] : r[i + nv];
                r[i] = keep + __shfl_xor_sync(0xffffffffu, send, o);
            }
        }
    }
    // lane holds combo==lane: edge = lane>>3, head = lane&7
    int myh = lane & 7;
    float e = 0.f;
    if (val)
        e = __expf(r[0] + qb_s[myh] + spdw_s[(pkl >> 20) * 8 + myh]);
    ss += e;

#pragma unroll
    for (int ed = 0; ed < 4; ed++) {
#pragma unroll
        for (int h = 0; h < HH; h++) {
            float eh = __shfl_sync(0xffffffffu, e, ed * 8 + h);
            ull e2 = bcast2(eh);
#pragma unroll
            for (int i = 0; i < 4; i++)
                acc[h][i] = ffma2(e2, xv[ed].u[i], acc[h][i]);
        }
    }
}

// ---------------- fused init: zero scratch + transpose Wq/Wv ----------------
__global__ void __launch_bounds__(256) k_init(const float* __restrict__ Wq,
                                              const float* __restrict__ Wv) {
    __shared__ float tsm[32][33];
    int b = blockIdx.x;
    if (b < 40) {
        int i = b * 256 + threadIdx.x;
        if (i < ND*PADH) g_histP[i] = 0;
        if (i < ND*8) { g_F1[i] = 0u; g_F2[i] = 0u; g_F3[i] = 0u; }
        if (i == 0) g_nlist = 0;
    } else {
        int bb = b - 40;
        int z = bb >> 6, rem = bb & 63;
        int bx = rem & 7, by = rem >> 3;
        const float* W = z ? Wv : Wq;
        float*       O = z ? g_WvT : g_WqT;
        int tx = threadIdx.x & 31, ty0 = threadIdx.x >> 5;
#pragma unroll
        for (int j = 0; j < 4; j++) {
            int ty = ty0 + j * 8;
            tsm[ty][tx] = W[(by * 32 + ty) * CCH + bx * 32 + tx];
        }
        __syncthreads();
#pragma unroll
        for (int j = 0; j < 4; j++) {
            int ty = ty0 + j * 8;
            O[(bx * 32 + ty) * CCH + by * 32 + tx] = tsm[tx][ty];
        }
    }
}

// dst histogram via shared-memory aggregation; src<256 list; F1 seed
__global__ void __launch_bounds__(256) k_prep(const int* __restrict__ src,
                                              const int* __restrict__ dst) {
    __shared__ int sh[ND];
    int t = threadIdx.x;
    sh[t] = 0;
    __syncthreads();
    int chunk = (EE + gridDim.x - 1) / gridDim.x;
    int start = blockIdx.x * chunk;
    int end   = min(EE, start + chunk);
    for (int i = start + t; i < end; i += 256) {
        int d = dst[i], s = src[i];
        atomicAdd(&sh[d], 1);
        if (s < ND) {
            int p = atomicAdd(&g_nlist, 1);
            g_list[p] = i;
            atomicOr(&g_F1[d * 8 + (s >> 5)], 1u << (s & 31));
        }
    }
    __syncthreads();
    if (sh[t]) atomicAdd(&g_histP[t * PADH], sh[t]);
}

// fused: parallel exclusive scan + both BFS steps (single CTA)
__global__ void __launch_bounds__(256) k_mid(const int* __restrict__ src,
                                             const int* __restrict__ dst) {
    int t = threadIdx.x, lane = t & 31, w = t >> 5;
    int v = g_histP[t * PADH];
    int xs = v;
#pragma unroll
    for (int o = 1; o < 32; o <<= 1) {
        int y = __shfl_up_sync(0xffffffffu, xs, o);
        if (lane >= o) xs += y;
    }
    __shared__ int ws[8], wb[8];
    if (lane == 31) ws[w] = xs;
    __syncthreads();
    if (t == 0) { int a = 0; for (int i = 0; i < 8; i++) { wb[i] = a; a += ws[i]; } }
    __syncthreads();
    int excl = xs + wb[w] - v;
    g_base[t] = excl;
    g_cnt[t]  = v;
    g_offP[t * PADH] = excl;
    __syncthreads();

    int n = g_nlist;
    for (int i = t; i < n; i += 256) {
        int e = g_list[i];
        int s = src[e], dd = dst[e];
#pragma unroll
        for (int w2 = 0; w2 < 8; w2++) {
            unsigned vv = g_F1[s * 8 + w2];
            if (vv) atomicOr(&g_F2[dd * 8 + w2], vv);
        }
    }
    __threadfence();
    __syncthreads();
    for (int i = t; i < n; i += 256) {
        int e = g_list[i];
        int s = src[e], dd = dst[e];
#pragma unroll
        for (int w2 = 0; w2 < 8; w2++) {
            unsigned vv = __ldcg(&g_F2[s * 8 + w2]);
            if (vv) atomicOr(&g_F3[dd * 8 + w2], vv);
        }
    }
}

// counting-sort scatter (block-reserved ranges), packing (spd<<20)|src
__global__ void __launch_bounds__(256) k_scatter(const int* __restrict__ src,
                                                 const int* __restrict__ dst) {
    __shared__ int shCnt[ND];
    __shared__ int shBase[ND];
    int t = threadIdx.x;
    shCnt[t] = 0;
    __syncthreads();
    int chunk = (EE + gridDim.x - 1) / gridDim.x;
    int start = blockIdx.x * chunk;
    int end   = min(EE, start + chunk);
    for (int i = start + t; i < end; i += 256) atomicAdd(&shCnt[dst[i]], 1);
    __syncthreads();
    int c = shCnt[t];
    shBase[t] = c ? atomicAdd(&g_offP[t * PADH], c) : 0;
    __syncthreads();
    shCnt[t] = 0;
    __syncthreads();
    for (int i = start + t; i < end; i += 256) {
        int d = dst[i], s = src[i];
        int loc = atomicAdd(&shCnt[d], 1);
        int p = shBase[d] + loc;
        int spd = 4;
        if (s < ND) {
            unsigned msk = 1u << (d & 31);
            int w = d >> 5;
            if      (g_F1[s * 8 + w] & msk) spd = 1;
            else if (g_F2[s * 8 + w] & msk) spd = 2;
            else if (g_F3[s * 8 + w] & msk) spd = 3;
        }
        g_pack[p] = s | (spd << 20);
    }
}

// fused: Qd[d] = x[d]@Wq^T+bq (into smem), then qt/qb
__global__ void __launch_bounds__(256) k_qdqt(const float* __restrict__ x,
                                              const float* __restrict__ bq,
                                              const float* __restrict__ Wk,
                                              const float* __restrict__ bk) {
    int d = blockIdx.x, c = threadIdx.x;
    __shared__ float xs[CCH];
    __shared__ float qd[CCH];
    xs[c] = x[d * CCH + c];
    __syncthreads();
    float a = bq[c];
#pragma unroll 4
    for (int k = 0; k < CCH; k++) a = fmaf(xs[k], g_WqT[k * CCH + c], a);
    qd[c] = a;
    __syncthreads();
#pragma unroll
    for (int h = 0; h < HH; h++) {
        float acc = 0.f;
#pragma unroll 8
        for (int j = 0; j < 32; j++)
            acc = fmaf(qd[h * 32 + j], Wk[(h * 32 + j) * CCH + c], acc);
        g_qt[(d * HH + h) * CCH + c] = FSCALE * acc;
        if (c == 0) {
            float qb = 0.f;
            for (int j = 0; j < 32; j++) qb += qd[h * 32 + j] * bk[h * 32 + j];
            g_qb[d * HH + h] = FSCALE * qb;
        }
    }
}

// ---------------- main: warp-per-4-edges, cp.async double buffer ------------
__global__ void __launch_bounds__(128, 2) k_main(const float* __restrict__ x,
                                                 const float* __restrict__ spd_w) {
    int d   = blockIdx.x >> 2;
    int cb  = blockIdx.x & 3;
    int tid = threadIdx.x;
    int wid = tid >> 5, lane = tid & 31;
    int part = cb * 4 + wid;           // 0..15

    __shared__ float xring[4][2][4][ROWF];  // warp, buf, edge, swizzled row (36 KB)
    __shared__ int   pks[4][CAPW];
    __shared__ float spdw_s[40];
    __shared__ float qb_s[HH];
    if (tid < 40) spdw_s[tid] = spd_w[tid];
    if (tid < HH) qb_s[tid] = g_qb[d * HH + tid];
    __syncthreads();

    // per-thread qt for all 8 heads (channels lane*8 .. lane*8+7)
    ull q[HH][4];
#pragma unroll
    for (int h = 0; h < HH; h++) {
        U8 qv;
        load8(qv, g_qt + (d * HH + h) * CCH + lane * 8);
#pragma unroll
        for (int i = 0; i < 4; i++) q[h][i] = qv.u[i];
    }

    ull acc[HH][4];
#pragma unroll
    for (int h = 0; h < HH; h++)
#pragma unroll
        for (int i = 0; i < 4; i++) acc[h][i] = 0ull;
    float ss = 0.f;

    // contiguous chunk for this partial
    int b0 = g_base[d], cnt = g_cnt[d];
    int per = (cnt + NPW - 1) >> 4;
    int a   = b0 + part * per;
    int bnd = min(b0 + cnt, a + per);
    int n   = max(0, bnd - a);
    int nc  = min(n, CAPW);

    for (int j = lane; j < nc; j += 32) pks[wid][j] = g_pack[a + j];
    __syncwarp();

    unsigned soff = slot_off(lane);
    unsigned sw0 = (unsigned)__cvta_generic_to_shared(&xring[wid][0][0][0]);

    // issue one 4-edge group into buffer (g&1)
    auto issue_group = [&](int g, int G) {
        if (g < G) {
            unsigned sb = sw0 + (unsigned)(g & 1) * (4 * ROWF * 4);
#pragma unroll
            for (int ed = 0; ed < 4; ed++) {
                int idx = g * 4 + ed;
                int pk = (idx < nc) ? pks[wid][idx] : 0;
                const float* gp = x + (size_t)(pk & 0xFFFFF) * CCH + lane * 8;
                unsigned sa = sb + (unsigned)ed * (ROWF * 4) + soff;
                cpasync16(sa, gp);
                cpasync16(sa + 16, gp + 4);
            }
        }
        CP_COMMIT();
    };

    int G = (nc + 3) >> 2;
    issue_group(0, G);
    issue_group(1, G);

    for (int g = 0; g < G; g++) {
        CP_WAIT(1);
        U8 xv[4];
        {
            unsigned base = (unsigned)(g & 1) * (4 * ROWF) ;
#pragma unroll
            for (int ed = 0; ed < 4; ed++) {
                const float4* sp = (const float4*)((const char*)&xring[wid][0][0][0]
                                   + (size_t)(g & 1) * (4 * ROWF * 4)
                                   + (size_t)ed * (ROWF * 4) + soff);
                xv[ed].f4[0] = sp[0];
                xv[ed].f4[1] = sp[1];
            }
            (void)base;
        }
        int ie = g * 4 + (lane >> 3);
        bool val = ie < nc;
        int pkl = pks[wid][min(ie, max(nc - 1, 0))];
        issue_group(g + 2, G);
        batch_compute(xv, pkl, val, q, acc, ss, spdw_s, qb_s, lane);
    }
    CP_WAIT(0);

    // oversized-chunk fallback (statistically unreachable, correctness-safe)
    for (int gg = nc; gg < n; gg += 4) {
        int ie = gg + (lane >> 3);
        bool val = ie < n;
        int pkl = val ? g_pack[a + ie] : 0;
        U8 xv[4];
#pragma unroll
        for (int ed = 0; ed < 4; ed++) {
            int pk_ed = __shfl_sync(0xffffffffu, pkl, ed * 8);
            int ok = (gg + ed) < n;
            load8(xv[ed], x + (size_t)((ok ? pk_ed : 0) & 0xFFFFF) * CCH + lane * 8);
        }
        batch_compute(xv, pkl, val, q, acc, ss, spdw_s, qb_s, lane);
    }

    // per-head exp-sum: combos with same head live at lanes {h, h+8, h+16, h+24}
    ss += __shfl_xor_sync(0xffffffffu, ss, 8);
    ss += __shfl_xor_sync(0xffffffffu, ss, 16);
    if (lane < HH) g_pS[(d * NPW + part) * HH + lane] = ss;

    // write per-warp partials (unique slot -> plain stores)
    float* P = g_pB + (size_t)(d * NPW + part) * (HH * CCH) + lane * 8;
#pragma unroll
    for (int h = 0; h < HH; h++) {
        U8 tmp;
#pragma unroll
        for (int i = 0; i < 4; i++) tmp.u[i] = acc[h][i];
        float4* dst4 = (float4*)(P + h * CCH);
        dst4[0] = tmp.f4[0];
        dst4[1] = tmp.f4[1];
    }
}

// merge NPW partials per dst, normalize per head, Wv epilogue
__global__ void __launch_bounds__(256) k_merge(const float* __restrict__ bv) {
    int d = blockIdx.x, t = threadIdx.x;
    __shared__ float Bs[HH * CCH];
    __shared__ float inv[HH];
    if (t < HH) {
        float s = 0.f;
#pragma unroll
        for (int pp = 0; pp < NPW; pp++) s += g_pS[(d * NPW + pp) * HH + t];
        inv[t] = (s > 0.f) ? (1.f / s) : 0.f;
    }
    __syncthreads();
#pragma unroll
    for (int e = t; e < HH * CCH; e += 256) {
        float s = 0.f;
#pragma unroll
        for (int pp = 0; pp < NPW; pp++)
            s += g_pB[(size_t)(d * NPW + pp) * (HH * CCH) + e];
        Bs[e] = s * inv[e >> 8];
    }
    __syncthreads();
    int hh = t >> 5;
    float o = bv[t];
    const float* Bp = Bs + hh * CCH;
    const float* Wp = g_WvT + t;
#pragma unroll 4
    for (int k = 0; k < CCH; k++) o = fmaf(Wp[k * CCH], Bp[k], o);
    g_agg[d * CCH + t] = o;
}

// LayerNorm over v = agg + x (deg constant per row -> cancels exactly)
__global__ void __launch_bounds__(256) k_ln(const float* __restrict__ x,
                                            const float* __restrict__ gamma,
                                            const float* __restrict__ beta,
                                            float* __restrict__ out) {
    int row  = blockIdx.x * 8 + (threadIdx.x >> 5);
    int lane = threadIdx.x & 31;
    if (row >= NN) return;
    const float4* xp = (const float4*)(x + (size_t)row * CCH) + lane * 2;
    float4 A = xp[0], B = xp[1];
    float v[8] = {A.x, A.y, A.z, A.w, B.x, B.y, B.z, B.w};
    if (row < ND) {
        const float4* ap = (const float4*)(g_agg + row * CCH) + lane * 2;
        float4 C = ap[0], D = ap[1];
        v[0] += C.x; v[1] += C.y; v[2] += C.z; v[3] += C.w;
        v[4] += D.x; v[5] += D.y; v[6] += D.z; v[7] += D.w;
    }
    float s = 0.f;
#pragma unroll
    for (int r = 0; r < 8; r++) s += v[r];
#pragma unroll
    for (int o = 16; o >= 1; o >>= 1) s += __shfl_xor_sync(0xffffffffu, s, o);
    float mu = s * (1.f / 256.f);
    float q = 0.f;
#pragma unroll
    for (int r = 0; r < 8; r++) { float tt = v[r] - mu; q += tt * tt; }
#pragma unroll
    for (int o = 16; o >= 1; o >>= 1) q += __shfl_xor_sync(0xffffffffu, q, o);
    float rs = rsqrtf(q * (1.f / 256.f) + 1e-5f);

    const float4* gp = (const float4*)gamma + lane * 2;
    const float4* bp = (const float4*)beta  + lane * 2;
    float4 G0 = gp[0], G1 = gp[1], B0 = bp[0], B1 = bp[1];
    float g[8]  = {G0.x,G0.y,G0.z,G0.w,G1.x,G1.y,G1.z,G1.w};
    float be[8] = {B0.x,B0.y,B0.z,B0.w,B1.x,B1.y,B1.z,B1.w};
    float r0[8];
#pragma unroll
    for (int r = 0; r < 8; r++) r0[r] = (v[r] - mu) * rs * g[r] + be[r];
    float4* op = (float4*)(out + (size_t)row * CCH) + lane * 2;
    op[0] = make_float4(r0[0], r0[1], r0[2], r0[3]);
    op[1] = make_float4(r0[4], r0[5], r0[6], r0[7]);
}

// ---------------- launch ----------------------------------------------------
extern "C" void kernel_launch(void* const* d_in, const int* in_sizes, int n_in,
                              void* d_out, int out_size) {
    const float* x     = (const float*)d_in[0];
    const int*   src   = (const int*)  d_in[1];
    const int*   dst   = (const int*)  d_in[2];
    const float* Wq    = (const float*)d_in[3];
    const float* bq    = (const float*)d_in[4];
    const float* Wk    = (const float*)d_in[5];
    const float* bk    = (const float*)d_in[6];
    const float* Wv    = (const float*)d_in[7];
    const float* bv    = (const float*)d_in[8];
    const float* spd_w = (const float*)d_in[9];
    const float* gamma = (const float*)d_in[10];
    const float* beta  = (const float*)d_in[11];
    float* out = (float*)d_out;
    (void)in_sizes; (void)n_in; (void)out_size;

    k_init<<<168, 256>>>(Wq, Wv);
    k_prep<<<592, 256>>>(src, dst);
    k_mid<<<1, 256>>>(src, dst);
    k_scatter<<<592, 256>>>(src, dst);
    k_qdqt<<<ND, 256>>>(x, bq, Wk, bk);
    k_main<<<ND * 4, 128>>>(x, spd_w);
    k_merge<<<ND, 256>>>(bv);
    k_ln<<<(NN + 7) / 8, 256>>>(x, gamma, beta, out);
}

// round 12
// speedup vs baseline: 2.7677x; 1.0489x over previous
#include <cuda_runtime.h>
#include <math.h>

#define NN 50000
#define EE 300000
#define CCH 256
#define HH 8
#define ND 256
#define NPW 16                   // edge-chunks per dst (4 CTAs x 4 warps)
#define PADH 32                  // counter padding (ints) to spread L2 slices
#define CAPW 128                 // smem pack-cache entries per warp
#define ROWF 288                 // padded floats per edge row in smem ring
#define MAINB (ND*4)             // main CTAs
#define LNROWS 4                 // rows per LN block
#define FSCALE 0.17677669529663687f   // 1/sqrt(32)

typedef unsigned long long ull;

// ---------------- static device scratch (no runtime allocation) -------------
__device__ float    g_qt[ND*HH*CCH];
__device__ float    g_qb[ND*HH];
__device__ float    g_WqT[CCH*CCH];
__device__ float    g_WvT[CCH*CCH];
__device__ int      g_histP[ND*PADH];
__device__ int      g_offP[ND*PADH];
__device__ int      g_base[ND];
__device__ int      g_cnt[ND];
__device__ int      g_list[EE];
__device__ int      g_nlist;
__device__ int      g_pack[EE];
__device__ unsigned g_F1[ND*8];
__device__ unsigned g_F2[ND*8];
__device__ unsigned g_F3[ND*8];
__device__ float    g_pB[(size_t)ND*4*HH*CCH];   // per-CTA partials (8.4 MB)
__device__ float    g_pS4[ND*4*HH];
__device__ int      g_tick[ND];

// ---------------- packed f32x2 + cp.async helpers ---------------------------
__device__ __forceinline__ ull ffma2(ull a, ull b, ull c) {
    ull d;
    asm("fma.rn.f32x2 %0, %1, %2, %3;" : "=l"(d) : "l"(a), "l"(b), "l"(c));
    return d;
}
__device__ __forceinline__ ull bcast2(float e) {
    ull r;
    asm("mov.b64 %0, {%1, %1};" : "=l"(r) : "f"(e));
    return r;
}
__device__ __forceinline__ float sum2(ull v) {
    float2 f;
    asm("mov.b64 {%0, %1}, %2;" : "=f"(f.x), "=f"(f.y) : "l"(v));
    return f.x + f.y;
}
__device__ __forceinline__ void cpasync16(unsigned s, const void* g) {
    asm volatile("cp.async.cg.shared.global [%0], [%1], 16;" :: "r"(s), "l"(g));
}
#define CP_COMMIT() asm volatile("cp.async.commit_group;")
#define CP_WAIT(n)  asm volatile("cp.async.wait_group %0;" :: "n"(n))

union U8 { float4 f4[2]; ull u[4]; float f[8]; };

__device__ __forceinline__ void load8(U8& v, const float* p) {
    const float4* q = (const float4*)p;
    v.f4[0] = q[0];
    v.f4[1] = q[1];
}
__device__ __forceinline__ unsigned slot_off(int lane) {
    return (unsigned)(lane * 32 + ((lane >> 2) & 7) * 16);
}

// 4-edge batched compute (dots, butterfly reduce-scatter, exp, accumulation)
__device__ __forceinline__ void batch_compute(
    const U8 (&xv)[4], int pkl, bool val,
    const ull (&q)[HH][4], ull (&acc)[HH][4], float& ss,
    const float* spdw_s, const float* qb_s, int lane)
{
    float r[32];
#pragma unroll
    for (int ed = 0; ed < 4; ed++) {
#pragma unroll
        for (int h = 0; h < HH; h++) {
            ull dp = 0ull;
#pragma unroll
            for (int i = 0; i < 4; i++) dp = ffma2(q[h][i], xv[ed].u[i], dp);
            r[ed * 8 + h] = sum2(dp);
        }
    }
#pragma unroll
    for (int lev = 0; lev < 5; lev++) {
        const int o  = 16 >> lev;
        const int nv = 16 >> lev;
        bool hi = (lane & o) != 0;
#pragma unroll
        for (int i = 0; i < 16; i++) {
            if (i < nv) {
                float keep = hi ? r[i + nv] : r[i];
                float send = hi ? r[i] : r[i + nv];
                r[i] = keep + __shfl_xor_sync(0xffffffffu, send, o);
            }
        }
    }
    int myh = lane & 7;
    float e = 0.f;
    if (val)
        e = __expf(r[0] + qb_s[myh] + spdw_s[(pkl >> 20) * 8 + myh]);
    ss += e;

#pragma unroll
    for (int ed = 0; ed < 4; ed++) {
#pragma unroll
        for (int h = 0; h < HH; h++) {
            float eh = __shfl_sync(0xffffffffu, e, ed * 8 + h);
            ull e2 = bcast2(eh);
#pragma unroll
            for (int i = 0; i < 4; i++)
                acc[h][i] = ffma2(e2, xv[ed].u[i], acc[h][i]);
        }
    }
}

// LayerNorm of one row held as 8 values/lane across a warp; writes out.
__device__ __forceinline__ void ln_warp_row(float (&v)[8], int row, int lane,
                                            const float* gamma, const float* beta,
                                            float* out) {
    float s = 0.f;
#pragma unroll
    for (int r = 0; r < 8; r++) s += v[r];
#pragma unroll
    for (int o = 16; o >= 1; o >>= 1) s += __shfl_xor_sync(0xffffffffu, s, o);
    float mu = s * (1.f / 256.f);
    float qv = 0.f;
#pragma unroll
    for (int r = 0; r < 8; r++) { float t = v[r] - mu; qv += t * t; }
#pragma unroll
    for (int o = 16; o >= 1; o >>= 1) qv += __shfl_xor_sync(0xffffffffu, qv, o);
    float rs = rsqrtf(qv * (1.f / 256.f) + 1e-5f);
    const float4* gp = (const float4*)gamma + lane * 2;
    const float4* bp = (const float4*)beta  + lane * 2;
    float4 G0 = gp[0], G1 = gp[1], B0 = bp[0], B1 = bp[1];
    float g[8]  = {G0.x,G0.y,G0.z,G0.w,G1.x,G1.y,G1.z,G1.w};
    float be[8] = {B0.x,B0.y,B0.z,B0.w,B1.x,B1.y,B1.z,B1.w};
    float r0[8];
#pragma unroll
    for (int r = 0; r < 8; r++) r0[r] = (v[r] - mu) * rs * g[r] + be[r];
    float4* op = (float4*)(out + (size_t)row * CCH) + lane * 2;
    op[0] = make_float4(r0[0], r0[1], r0[2], r0[3]);
    op[1] = make_float4(r0[4], r0[5], r0[6], r0[7]);
}

// ---------------- fused init: zero scratch + transpose Wq/Wv ----------------
__global__ void __launch_bounds__(256) k_init(const float* __restrict__ Wq,
                                              const float* __restrict__ Wv) {
    __shared__ float tsm[32][33];
    int b = blockIdx.x;
    if (b < 40) {
        int i = b * 256 + threadIdx.x;
        if (i < ND*PADH) g_histP[i] = 0;
        if (i < ND*8) { g_F1[i] = 0u; g_F2[i] = 0u; g_F3[i] = 0u; }
        if (i < ND)   g_tick[i] = 0;
        if (i == 0)   g_nlist = 0;
    } else {
        int bb = b - 40;
        int z = bb >> 6, rem = bb & 63;
        int bx = rem & 7, by = rem >> 3;
        const float* W = z ? Wv : Wq;
        float*       O = z ? g_WvT : g_WqT;
        int tx = threadIdx.x & 31, ty0 = threadIdx.x >> 5;
#pragma unroll
        for (int j = 0; j < 4; j++) {
            int ty = ty0 + j * 8;
            tsm[ty][tx] = W[(by * 32 + ty) * CCH + bx * 32 + tx];
        }
        __syncthreads();
#pragma unroll
        for (int j = 0; j < 4; j++) {
            int ty = ty0 + j * 8;
            O[(bx * 32 + ty) * CCH + by * 32 + tx] = tsm[tx][ty];
        }
    }
}

// dst histogram; src<256 list; F1 seed
__global__ void __launch_bounds__(256) k_prep(const int* __restrict__ src,
                                              const int* __restrict__ dst) {
    __shared__ int sh[ND];
    int t = threadIdx.x;
    sh[t] = 0;
    __syncthreads();
    int chunk = (EE + gridDim.x - 1) / gridDim.x;
    int start = blockIdx.x * chunk;
    int end   = min(EE, start + chunk);
    for (int i = start + t; i < end; i += 256) {
        int d = dst[i], s = src[i];
        atomicAdd(&sh[d], 1);
        if (s < ND) {
            int p = atomicAdd(&g_nlist, 1);
            g_list[p] = i;
            atomicOr(&g_F1[d * 8 + (s >> 5)], 1u << (s & 31));
        }
    }
    __syncthreads();
    if (sh[t]) atomicAdd(&g_histP[t * PADH], sh[t]);
}

// fused: parallel exclusive scan + both BFS steps (single CTA)
__global__ void __launch_bounds__(256) k_mid(const int* __restrict__ src,
                                             const int* __restrict__ dst) {
    int t = threadIdx.x, lane = t & 31, w = t >> 5;
    int v = g_histP[t * PADH];
    int xs = v;
#pragma unroll
    for (int o = 1; o < 32; o <<= 1) {
        int y = __shfl_up_sync(0xffffffffu, xs, o);
        if (lane >= o) xs += y;
    }
    __shared__ int ws[8], wb[8];
    if (lane == 31) ws[w] = xs;
    __syncthreads();
    if (t == 0) { int a = 0; for (int i = 0; i < 8; i++) { wb[i] = a; a += ws[i]; } }
    __syncthreads();
    int excl = xs + wb[w] - v;
    g_base[t] = excl;
    g_cnt[t]  = v;
    g_offP[t * PADH] = excl;
    __syncthreads();

    int n = g_nlist;
    for (int i = t; i < n; i += 256) {
        int e = g_list[i];
        int s = src[e], dd = dst[e];
#pragma unroll
        for (int w2 = 0; w2 < 8; w2++) {
            unsigned vv = g_F1[s * 8 + w2];
            if (vv) atomicOr(&g_F2[dd * 8 + w2], vv);
        }
    }
    __threadfence();
    __syncthreads();
    for (int i = t; i < n; i += 256) {
        int e = g_list[i];
        int s = src[e], dd = dst[e];
#pragma unroll
        for (int w2 = 0; w2 < 8; w2++) {
            unsigned vv = __ldcg(&g_F2[s * 8 + w2]);
            if (vv) atomicOr(&g_F3[dd * 8 + w2], vv);
        }
    }
}

// counting-sort scatter, packing (spd<<20)|src
__global__ void __launch_bounds__(256) k_scatter(const int* __restrict__ src,
                                                 const int* __restrict__ dst) {
    __shared__ int shCnt[ND];
    __shared__ int shBase[ND];
    int t = threadIdx.x;
    shCnt[t] = 0;
    __syncthreads();
    int chunk = (EE + gridDim.x - 1) / gridDim.x;
    int start = blockIdx.x * chunk;
    int end   = min(EE, start + chunk);
    for (int i = start + t; i < end; i += 256) atomicAdd(&shCnt[dst[i]], 1);
    __syncthreads();
    int c = shCnt[t];
    shBase[t] = c ? atomicAdd(&g_offP[t * PADH], c) : 0;
    __syncthreads();
    shCnt[t] = 0;
    __syncthreads();
    for (int i = start + t; i < end; i += 256) {
        int d = dst[i], s = src[i];
        int loc = atomicAdd(&shCnt[d], 1);
        int p = shBase[d] + loc;
        int spd = 4;
        if (s < ND) {
            unsigned msk = 1u << (d & 31);
            int w = d >> 5;
            if      (g_F1[s * 8 + w] & msk) spd = 1;
            else if (g_F2[s * 8 + w] & msk) spd = 2;
            else if (g_F3[s * 8 + w] & msk) spd = 3;
        }
        g_pack[p] = s | (spd << 20);
    }
}

// fused: Qd = x@Wq^T+bq (smem), then qt/qb
__global__ void __launch_bounds__(256) k_qdqt(const float* __restrict__ x,
                                              const float* __restrict__ bq,
                                              const float* __restrict__ Wk,
                                              const float* __restrict__ bk) {
    int d = blockIdx.x, c = threadIdx.x;
    __shared__ float xs[CCH];
    __shared__ float qd[CCH];
    xs[c] = x[d * CCH + c];
    __syncthreads();
    float a = bq[c];
#pragma unroll 8
    for (int k = 0; k < CCH; k++) a = fmaf(xs[k], g_WqT[k * CCH + c], a);
    qd[c] = a;
    __syncthreads();
#pragma unroll
    for (int h = 0; h < HH; h++) {
        float acc = 0.f;
#pragma unroll 8
        for (int j = 0; j < 32; j++)
            acc = fmaf(qd[h * 32 + j], Wk[(h * 32 + j) * CCH + c], acc);
        g_qt[(d * HH + h) * CCH + c] = FSCALE * acc;
        if (c == 0) {
            float qb = 0.f;
            for (int j = 0; j < 32; j++) qb += qd[h * 32 + j] * bk[h * 32 + j];
            g_qb[d * HH + h] = FSCALE * qb;
        }
    }
}

// ------- fused main: attention partials + last-CTA merge/epilogue/LN,
// ------- plus independent LN blocks for rows >= ND.
__global__ void __launch_bounds__(128, 2) k_fused(const float* __restrict__ x,
                                                  const float* __restrict__ spd_w,
                                                  const float* __restrict__ bv,
                                                  const float* __restrict__ gamma,
                                                  const float* __restrict__ beta,
                                                  float* __restrict__ out) {
    int b   = blockIdx.x;
    int tid = threadIdx.x;
    int wid = tid >> 5, lane = tid & 31;

    // ---------- pure-LN blocks (rows >= ND depend only on x) ----------
    if (b >= MAINB) {
        int row = ND + (b - MAINB) * LNROWS + wid;
        if (row >= NN) return;
        const float4* xp = (const float4*)(x + (size_t)row * CCH) + lane * 2;
        float4 A = xp[0], B = xp[1];
        float v[8] = {A.x, A.y, A.z, A.w, B.x, B.y, B.z, B.w};
        ln_warp_row(v, row, lane, gamma, beta, out);
        return;
    }

    // ---------- attention partial ----------
    int d  = b >> 2;
    int cb = b & 3;
    int part = cb * 4 + wid;           // 0..15

    __shared__ float xring[4][2][4][ROWF];  // 36 KB (reused as combine buffer)
    __shared__ int   pks[4][CAPW];          // 2 KB (reused for exp-sums)
    __shared__ float spdw_s[40];
    __shared__ float qb_s[HH];
    __shared__ int   sm_old;
    if (tid < 40) spdw_s[tid] = spd_w[tid];
    if (tid < HH) qb_s[tid] = g_qb[d * HH + tid];
    __syncthreads();

    ull q[HH][4];
#pragma unroll
    for (int h = 0; h < HH; h++) {
        U8 qv;
        load8(qv, g_qt + (d * HH + h) * CCH + lane * 8);
#pragma unroll
        for (int i = 0; i < 4; i++) q[h][i] = qv.u[i];
    }

    ull acc[HH][4];
#pragma unroll
    for (int h = 0; h < HH; h++)
#pragma unroll
        for (int i = 0; i < 4; i++) acc[h][i] = 0ull;
    float ss = 0.f;

    int b0 = g_base[d], cnt = g_cnt[d];
    int per = (cnt + NPW - 1) >> 4;
    int a   = b0 + part * per;
    int bnd = min(b0 + cnt, a + per);
    int n   = max(0, bnd - a);
    int nc  = min(n, CAPW);

    for (int j = lane; j < nc; j += 32) pks[wid][j] = g_pack[a + j];
    __syncwarp();

    unsigned soff = slot_off(lane);
    unsigned sw0 = (unsigned)__cvta_generic_to_shared(&xring[wid][0][0][0]);

    auto issue_group = [&](int g, int G) {
        if (g < G) {
            unsigned sb = sw0 + (unsigned)(g & 1) * (4 * ROWF * 4);
#pragma unroll
            for (int ed = 0; ed < 4; ed++) {
                int idx = g * 4 + ed;
                int pk = (idx < nc) ? pks[wid][idx] : 0;
                const float* gp = x + (size_t)(pk & 0xFFFFF) * CCH + lane * 8;
                unsigned sa = sb + (unsigned)ed * (ROWF * 4) + soff;
                cpasync16(sa, gp);
                cpasync16(sa + 16, gp + 4);
            }
        }
        CP_COMMIT();
    };

    int G = (nc + 3) >> 2;
    issue_group(0, G);
    issue_group(1, G);

    for (int g = 0; g < G; g++) {
        CP_WAIT(1);
        U8 xv[4];
#pragma unroll
        for (int ed = 0; ed < 4; ed++) {
            const float4* sp = (const float4*)((const char*)&xring[wid][0][0][0]
                               + (size_t)(g & 1) * (4 * ROWF * 4)
                               + (size_t)ed * (ROWF * 4) + soff);
            xv[ed].f4[0] = sp[0];
            xv[ed].f4[1] = sp[1];
        }
        int ie = g * 4 + (lane >> 3);
        bool val = ie < nc;
        int pkl = pks[wid][min(ie, max(nc - 1, 0))];
        issue_group(g + 2, G);
        batch_compute(xv, pkl, val, q, acc, ss, spdw_s, qb_s, lane);
    }
    CP_WAIT(0);

    for (int gg = nc; gg < n; gg += 4) {   // oversized-chunk fallback
        int ie = gg + (lane >> 3);
        bool val = ie < n;
        int pkl = val ? g_pack[a + ie] : 0;
        U8 xv[4];
#pragma unroll
        for (int ed = 0; ed < 4; ed++) {
            int pk_ed = __shfl_sync(0xffffffffu, pkl, ed * 8);
            int ok = (gg + ed) < n;
            load8(xv[ed], x + (size_t)((ok ? pk_ed : 0) & 0xFFFFF) * CCH + lane * 8);
        }
        batch_compute(xv, pkl, val, q, acc, ss, spdw_s, qb_s, lane);
    }

    // per-head exp-sum within warp: lanes {h, h+8, h+16, h+24} share a head
    ss += __shfl_xor_sync(0xffffffffu, ss, 8);
    ss += __shfl_xor_sync(0xffffffffu, ss, 16);

    // ---------- in-CTA combine of 4 warps (reuse xring as smA) ----------
    __syncthreads();
    float* smA = (float*)xring;            // [4 warps][2048]
    float* smS = (float*)pks;              // exp-sums + inv
#pragma unroll
    for (int h = 0; h < HH; h++) {
        U8 tmp;
#pragma unroll
        for (int i = 0; i < 4; i++) tmp.u[i] = acc[h][i];
        float4* dp = (float4*)(smA + (wid * HH + h) * CCH + lane * 8);
        dp[0] = tmp.f4[0];
        dp[1] = tmp.f4[1];
    }
    if (lane < HH) smS[wid * 8 + lane] = ss;
    __syncthreads();

    // 128 threads fold 4 warp-slices into slice 0
    for (int j = tid; j < HH * CCH; j += 128) {
        float s = smA[j] + smA[2048 + j] + smA[4096 + j] + smA[6144 + j];
        smA[j] = s;
    }
    if (tid < HH) smS[tid] = smS[tid] + smS[8 + tid] + smS[16 + tid] + smS[24 + tid];
    __syncthreads();

    // write CTA partial
    {
        float* P = g_pB + (size_t)(d * 4 + cb) * (HH * CCH);
        for (int j = tid * 4; j < HH * CCH; j += 512)
            *(float4*)(P + j) = *(float4*)(smA + j);
        if (tid < HH) g_pS4[(d * 4 + cb) * HH + tid] = smS[tid];
    }
    __syncthreads();
    __threadfence();
    if (tid == 0) sm_old = atomicAdd(&g_tick[d], 1);
    __syncthreads();
    if (sm_old != 3) return;

    // ---------- last CTA: merge partials + epilogue + LN of row d ----------
#pragma unroll
    for (int pp = 0; pp < 4; pp++) {
        if (pp == cb) continue;
        const float* P = g_pB + (size_t)(d * 4 + pp) * (HH * CCH);
        for (int j = tid * 4; j < HH * CCH; j += 512) {
            float4 vv;
            vv.x = __ldcg(P + j);
            vv.y = __ldcg(P + j + 1);
            vv.z = __ldcg(P + j + 2);
            vv.w = __ldcg(P + j + 3);
            smA[j]     += vv.x;
            smA[j + 1] += vv.y;
            smA[j + 2] += vv.z;
            smA[j + 3] += vv.w;
        }
        if (tid < HH) smS[tid] += __ldcg(&g_pS4[(d * 4 + pp) * HH + tid]);
    }
    __syncthreads();
    if (tid < HH) smS[32 + tid] = (smS[tid] > 0.f) ? (1.f / smS[tid]) : 0.f;
    __syncthreads();

    // epilogue: each thread produces channels tid and tid+128
    int c0 = tid, c1 = tid + 128;
    float o0 = 0.f, o1 = 0.f;
    const float* B0 = smA + (c0 >> 5) * CCH;
    const float* B1 = smA + (c1 >> 5) * CCH;
#pragma unroll 4
    for (int k = 0; k < CCH; k++) {
        o0 = fmaf(g_WvT[k * CCH + c0], B0[k], o0);
        o1 = fmaf(g_WvT[k * CCH + c1], B1[k], o1);
    }
    o0 = o0 * smS[32 + (c0 >> 5)] + bv[c0];
    o1 = o1 * smS[32 + (c1 >> 5)] + bv[c1];

    // LN over v = o + x[d]  (deg constant per row cancels)
    float v0 = o0 + x[(size_t)d * CCH + c0];
    float v1 = o1 + x[(size_t)d * CCH + c1];
    float s = v0 + v1;
#pragma unroll
    for (int o = 16; o >= 1; o >>= 1) s += __shfl_xor_sync(0xffffffffu, s, o);
    __shared__ float red[8];
    if (lane == 0) red[wid] = s;
    __syncthreads();
    float tot = red[0] + red[1] + red[2] + red[3];
    float mu = tot * (1.f / 256.f);
    float q0 = (v0 - mu) * (v0 - mu) + (v1 - mu) * (v1 - mu);
#pragma unroll
    for (int o = 16; o >= 1; o >>= 1) q0 += __shfl_xor_sync(0xffffffffu, q0, o);
    __syncthreads();
    if (lane == 0) red[wid] = q0;
    __syncthreads();
    float var = (red[0] + red[1] + red[2] + red[3]) * (1.f / 256.f);
    float rs = rsqrtf(var + 1e-5f);
    out[(size_t)d * CCH + c0] = (v0 - mu) * rs * gamma[c0] + beta[c0];
    out[(size_t)d * CCH + c1] = (v1 - mu) * rs * gamma[c1] + beta[c1];
}

// ---------------- launch ----------------------------------------------------
extern "C" void kernel_launch(void* const* d_in, const int* in_sizes, int n_in,
                              void* d_out, int out_size) {
    const float* x     = (const float*)d_in[0];
    const int*   src   = (const int*)  d_in[1];
    const int*   dst   = (const int*)  d_in[2];
    const float* Wq    = (const float*)d_in[3];
    const float* bq    = (const float*)d_in[4];
    const float* Wk    = (const float*)d_in[5];
    const float* bk    = (const float*)d_in[6];
    const float* Wv    = (const float*)d_in[7];
    const float* bv    = (const float*)d_in[8];
    const float* spd_w = (const float*)d_in[9];
    const float* gamma = (const float*)d_in[10];
    const float* beta  = (const float*)d_in[11];
    float* out = (float*)d_out;
    (void)in_sizes; (void)n_in; (void)out_size;

    int lnb = (NN - ND + LNROWS - 1) / LNROWS;   // 12436
    k_init<<<168, 256>>>(Wq, Wv);
    k_prep<<<592, 256>>>(src, dst);
    k_mid<<<1, 256>>>(src, dst);
    k_scatter<<<592, 256>>>(src, dst);
    k_qdqt<<<ND, 256>>>(x, bq, Wk, bk);
    k_fused<<<MAINB + lnb, 128>>>(x, spd_w, bv, gamma, beta, out);
}